// round 7
// baseline (speedup 1.0000x reference)
#include <cuda_runtime.h>
#include <cstdint>

// Problem constants
#define B_  32
#define H_  4
#define L_  2048
#define D_  64
#define N_  32
#define P_  64
#define WN  63          // win_num
#define II  64          // N * win

#define WX_ELEMS 33030144   // B*H*II*WN*D
#define M_V      129024     // B*II*WN
#define NBHW     8064       // B*H*WN
#define OUT_ELEMS 16777216  // B*L*H*D

// Scratch (static device globals — allocation-free per harness rules)
__device__ float g_wx[WX_ELEMS];   // [b][h][i][w][d]
__device__ float g_v [WX_ELEMS];   // [b][i][w][h*64+d]
__device__ float g_adj[WX_ELEMS];  // [b][h][w][i][j]
__device__ float g_o [WX_ELEMS];   // [b][h][w][i][d]

// ---------------------------------------------------------------------------
// tf32 helpers
// ---------------------------------------------------------------------------
__device__ __forceinline__ uint32_t f2tf32(float x) {
    uint32_t r;
    asm("cvt.rna.tf32.f32 %0, %1;" : "=r"(r) : "f"(x));
    return r;
}
__device__ __forceinline__ void split_tf32(float x, uint32_t& hi, uint32_t& lo) {
    asm("cvt.rna.tf32.f32 %0, %1;" : "=r"(hi) : "f"(x));
    float l = x - __uint_as_float(hi);
    asm("cvt.rna.tf32.f32 %0, %1;" : "=r"(lo) : "f"(l));
}
__device__ __forceinline__ void mma8(float* d, const uint32_t* a, const uint32_t* b) {
    asm volatile(
        "mma.sync.aligned.m16n8k8.row.col.f32.tf32.tf32.f32 "
        "{%0,%1,%2,%3}, {%4,%5,%6,%7}, {%8,%9}, {%0,%1,%2,%3};"
        : "+f"(d[0]), "+f"(d[1]), "+f"(d[2]), "+f"(d[3])
        : "r"(a[0]), "r"(a[1]), "r"(a[2]), "r"(a[3]), "r"(b[0]), "r"(b[1]));
}
// 3xTF32: d += a*b with near-fp32 accuracy (lo*hi + hi*lo + hi*hi)
__device__ __forceinline__ void mma3(float* d, const uint32_t* ah, const uint32_t* al,
                                     const uint32_t* bh, const uint32_t* bl) {
    mma8(d, al, bh);
    mma8(d, ah, bl);
    mma8(d, ah, bh);
}

// smem bank swizzle for [64][64] tiles: pc = c ^ ((r&7)*4)
__device__ __forceinline__ int sw(int r, int c) { return c ^ ((r & 7) << 2); }

// ---------------------------------------------------------------------------
// 1. Gather wx, coalesced: one block per (bh, n); stage 64x64 x-tile in smem.
// ---------------------------------------------------------------------------
__global__ __launch_bounds__(256) void k_build_wx(const float* __restrict__ x) {
    __shared__ float xs[64][65];
    int bid = blockIdx.x;          // bh*32 + n, 4096 blocks
    int bh  = bid >> 5;
    int n   = bid & 31;
    int tid = threadIdx.x;
#pragma unroll
    for (int it = 0; it < 16; ++it) {
        int i2 = tid + it * 256;
        int rr = i2 >> 6, cc = i2 & 63;
        xs[rr][cc] = x[(bh * L_ + n * P_ + rr) * D_ + cc];
    }
    __syncthreads();
    float* dst = g_wx + bh * 258048 + n * 8064;
    for (int j = tid; j < 8064; j += 256) {
        int d  = j / 126;
        int r2 = j - d * 126;
        int row = (r2 >> 1) + (r2 & 1);     // w + e
        dst[j] = xs[row][d];
    }
}

// ---------------------------------------------------------------------------
// 2. Fused per (b,h,w): Q=XW1+b1, K=XW2+b2, A=QK^T (all 3xTF32 tensor core),
//    exact top-32 |.| mask, tanh, L1 row-normalize -> g_adj.
//    All tiles [64][64] with XOR bank swizzle (conflict-free A-frags).
// ---------------------------------------------------------------------------
__global__ __launch_bounds__(256) void k_qk_adj(const float* __restrict__ W1,
                                                const float* __restrict__ b1,
                                                const float* __restrict__ W2,
                                                const float* __restrict__ b2) {
    __shared__ float Xs[64][64];
    __shared__ float U1[64][64];
    __shared__ float U2[64][64];
    int tid = threadIdx.x;
    int bid = blockIdx.x;
    int w   = bid % WN;
    int bh  = bid / WN;
#pragma unroll
    for (int it = 0; it < 16; ++it) {
        int i2 = tid + it * 256;
        int rr = i2 >> 6, cc = i2 & 63;
        int pc = sw(rr, cc);
        Xs[rr][pc] = g_wx[((bh * II + rr) * WN + w) * D_ + cc];
        U1[rr][pc] = W1[i2];
        U2[rr][pc] = W2[i2];
    }
    __syncthreads();

    int warp = tid >> 5, lane = tid & 31;
    int g = lane >> 2, tq = lane & 3;

    // ---- Phase 1: warps 0-3 -> Q strips, warps 4-7 -> K strips (16x64 each)
    {
        int ms = (warp & 3) * 16;
        bool isK = warp >= 4;
        float (*Wop)[64] = isK ? U2 : U1;
        float acc[8][4];
#pragma unroll
        for (int nt = 0; nt < 8; ++nt)
#pragma unroll
            for (int c = 0; c < 4; ++c) acc[nt][c] = 0.f;
#pragma unroll
        for (int ks = 0; ks < 8; ++ks) {
            int k0 = ks * 8;
            uint32_t ah[4], al[4];
            split_tf32(Xs[ms + g]    [sw(ms + g,     k0 + tq)],     ah[0], al[0]);
            split_tf32(Xs[ms + g + 8][sw(ms + g + 8, k0 + tq)],     ah[1], al[1]);
            split_tf32(Xs[ms + g]    [sw(ms + g,     k0 + tq + 4)], ah[2], al[2]);
            split_tf32(Xs[ms + g + 8][sw(ms + g + 8, k0 + tq + 4)], ah[3], al[3]);
#pragma unroll
            for (int nt = 0; nt < 8; ++nt) {
                uint32_t bhv[2], blv[2];
                split_tf32(Wop[k0 + tq]    [sw(k0 + tq,     nt * 8 + g)], bhv[0], blv[0]);
                split_tf32(Wop[k0 + tq + 4][sw(k0 + tq + 4, nt * 8 + g)], bhv[1], blv[1]);
                mma3(acc[nt], ah, al, bhv, blv);
            }
        }
        __syncthreads();   // all W1/W2 reads done before overwrite
        const float* bias = isK ? b2 : b1;
        float (*Udst)[64] = isK ? U2 : U1;
#pragma unroll
        for (int nt = 0; nt < 8; ++nt) {
            int n0 = nt * 8 + 2 * tq;
            float bb0 = bias[n0], bb1 = bias[n0 + 1];
            Udst[ms + g]    [sw(ms + g,     n0)]     = acc[nt][0] + bb0;
            Udst[ms + g]    [sw(ms + g,     n0 + 1)] = acc[nt][1] + bb1;
            Udst[ms + g + 8][sw(ms + g + 8, n0)]     = acc[nt][2] + bb0;
            Udst[ms + g + 8][sw(ms + g + 8, n0 + 1)] = acc[nt][3] + bb1;
        }
        __syncthreads();
    }

    // ---- Phase 2: A = Q K^T. Warp tile: 16 x 32.
    {
        int ms = (warp & 3) * 16;
        int nh = (warp >> 2) * 32;
        float acc[4][4];
#pragma unroll
        for (int nt = 0; nt < 4; ++nt)
#pragma unroll
            for (int c = 0; c < 4; ++c) acc[nt][c] = 0.f;
#pragma unroll
        for (int ks = 0; ks < 8; ++ks) {
            int k0 = ks * 8;
            uint32_t ah[4], al[4];
            split_tf32(U1[ms + g]    [sw(ms + g,     k0 + tq)],     ah[0], al[0]);
            split_tf32(U1[ms + g + 8][sw(ms + g + 8, k0 + tq)],     ah[1], al[1]);
            split_tf32(U1[ms + g]    [sw(ms + g,     k0 + tq + 4)], ah[2], al[2]);
            split_tf32(U1[ms + g + 8][sw(ms + g + 8, k0 + tq + 4)], ah[3], al[3]);
#pragma unroll
            for (int nt = 0; nt < 4; ++nt) {
                int j0 = nh + nt * 8 + g;
                uint32_t bhv[2], blv[2];
                split_tf32(U2[j0][sw(j0, k0 + tq)],     bhv[0], blv[0]);
                split_tf32(U2[j0][sw(j0, k0 + tq + 4)], bhv[1], blv[1]);
                mma3(acc[nt], ah, al, bhv, blv);
            }
        }
#pragma unroll
        for (int nt = 0; nt < 4; ++nt) {
            int n0 = nh + nt * 8 + 2 * tq;
            Xs[ms + g]    [sw(ms + g,     n0)]     = acc[nt][0];
            Xs[ms + g]    [sw(ms + g,     n0 + 1)] = acc[nt][1];
            Xs[ms + g + 8][sw(ms + g + 8, n0)]     = acc[nt][2];
            Xs[ms + g + 8][sw(ms + g + 8, n0 + 1)] = acc[nt][3];
        }
        __syncthreads();
    }

    // ---- ranking: exact top_k tie semantics; tanh; L1 normalize ----
    int adjbase = bid * 4096;
    for (int r8 = 0; r8 < 8; ++r8) {
        int row = warp * 8 + r8;
        float a1 = Xs[row][sw(row, lane)];
        float a2 = Xs[row][sw(row, lane + 32)];
        float ab1 = fabsf(a1), ab2 = fabsf(a2);
        int c1 = 0, c2 = 0;
#pragma unroll 8
        for (int j = 0; j < 64; ++j) {
            float vj = fabsf(Xs[row][sw(row, j)]);
            c1 += (vj < ab1) || (vj == ab1 && j < lane);
            c2 += (vj < ab2) || (vj == ab2 && j < lane + 32);
        }
        float t1 = (c1 >= 32) ? tanhf(a1) : 0.f;
        float t2 = (c2 >= 32) ? tanhf(a2) : 0.f;
        float s = fabsf(t1) + fabsf(t2);
#pragma unroll
        for (int off = 16; off; off >>= 1) s += __shfl_xor_sync(0xffffffffu, s, off);
        float inv = 1.f / fmaxf(s, 1e-12f);
        g_adj[adjbase + row * 64 + lane]      = t1 * inv;
        g_adj[adjbase + row * 64 + lane + 32] = t2 * inv;
    }
}

// ---------------------------------------------------------------------------
// 3. v = v_in @ Wv + bv  (3xTF32 tensor core). 64 rows x 256 cols per block.
//    As padded to stride 36 (conflict-free frag loads); Bs fp32, split in regs.
// ---------------------------------------------------------------------------
__global__ __launch_bounds__(256) void k_v2(const float* __restrict__ Wv,
                                            const float* __restrict__ bv) {
    __shared__ float As[64][36];
    __shared__ __align__(16) float Bs[32][264];
    int tid  = threadIdx.x;
    int m0   = blockIdx.x * 64;
    int b    = blockIdx.x / 63;
    int rem0 = (blockIdx.x - b * 63) * 64;
    int warp = tid >> 5, lane = tid & 31;
    int g = lane >> 2, tq = lane & 3;
    int ms = (warp & 3) * 16;
    int nh = (warp >> 2) * 128;
    float acc[16][4];
#pragma unroll
    for (int nt = 0; nt < 16; ++nt)
#pragma unroll
        for (int c = 0; c < 4; ++c) acc[nt][c] = 0.f;

    for (int ch = 0; ch < 8; ++ch) {       // global k = ch*32 + kk; h = ch>>1
#pragma unroll
        for (int it = 0; it < 8; ++it) {   // As: 64x32
            int i2 = tid + it * 256;
            int rr = i2 >> 5, kkc = i2 & 31;
            int rem = rem0 + rr;
            int i  = rem / WN;
            int ww = rem - i * WN;
            As[rr][kkc] = g_wx[(((b * H_ + (ch >> 1)) * II + i) * WN + ww) * D_ +
                               (ch & 1) * 32 + kkc];
        }
#pragma unroll
        for (int it = 0; it < 8; ++it) {   // Bs: 32x256 fp32
            int i4 = tid + it * 256;
            int r  = i4 >> 6;
            int c  = (i4 & 63) * 4;
            *(float4*)&Bs[r][c] = *(const float4*)&Wv[(ch * 32 + r) * 256 + c];
        }
        __syncthreads();
#pragma unroll
        for (int ks = 0; ks < 4; ++ks) {
            int k0 = ks * 8;
            uint32_t ah[4], al[4];
            split_tf32(As[ms + g][k0 + tq],         ah[0], al[0]);
            split_tf32(As[ms + g + 8][k0 + tq],     ah[1], al[1]);
            split_tf32(As[ms + g][k0 + tq + 4],     ah[2], al[2]);
            split_tf32(As[ms + g + 8][k0 + tq + 4], ah[3], al[3]);
#pragma unroll
            for (int nt = 0; nt < 16; ++nt) {
                int n0 = nh + nt * 8 + g;
                uint32_t bhv[2], blv[2];
                split_tf32(Bs[k0 + tq][n0],     bhv[0], blv[0]);
                split_tf32(Bs[k0 + tq + 4][n0], bhv[1], blv[1]);
                mma3(acc[nt], ah, al, bhv, blv);
            }
        }
        __syncthreads();
    }
#pragma unroll
    for (int nt = 0; nt < 16; ++nt) {
        int n0 = nh + nt * 8 + 2 * tq;
        float bb0 = bv[n0], bb1 = bv[n0 + 1];
        g_v[(m0 + ms + g) * 256 + n0]         = acc[nt][0] + bb0;
        g_v[(m0 + ms + g) * 256 + n0 + 1]     = acc[nt][1] + bb1;
        g_v[(m0 + ms + g + 8) * 256 + n0]     = acc[nt][2] + bb0;
        g_v[(m0 + ms + g + 8) * 256 + n0 + 1] = acc[nt][3] + bb1;
    }
}

// ---------------------------------------------------------------------------
// 4. loss = mean_{b,h,i,j} var_w(adj)   (ddof=0, two-pass)
// ---------------------------------------------------------------------------
__global__ void k_loss_zero(float* __restrict__ out) { out[OUT_ELEMS] = 0.f; }

__global__ __launch_bounds__(256) void k_loss(float* __restrict__ out) {
    int idx = blockIdx.x * 256 + threadIdx.x;  // over B*H*64*64 = 524288
    int bh  = idx >> 12;
    int ij  = idx & 4095;
    const float* p = g_adj + bh * (WN * 4096) + ij;
    float s1 = 0.f;
#pragma unroll 7
    for (int w = 0; w < WN; ++w) s1 += p[w * 4096];
    float m = s1 * (1.f / 63.f);
    float s2 = 0.f;
#pragma unroll 7
    for (int w = 0; w < WN; ++w) { float dv = p[w * 4096] - m; s2 += dv * dv; }
    float var = s2 * (1.f / 63.f);
    __shared__ float red[256];
    red[threadIdx.x] = var;
    __syncthreads();
    for (int off = 128; off; off >>= 1) {
        if (threadIdx.x < off) red[threadIdx.x] += red[threadIdx.x + off];
        __syncthreads();
    }
    if (threadIdx.x == 0) atomicAdd(out + OUT_ELEMS, red[0] * (1.f / 524288.f));
}

// ---------------------------------------------------------------------------
// 5. Per (b,h,w): O = A_w @ V_w (3xTF32 tensor core).
//    V_w[j][d] = g_v[b, j, w, h*64+d].  As stride 68, Vs stride 72: both
//    conflict-free for the fragment patterns.
// ---------------------------------------------------------------------------
__global__ __launch_bounds__(256) void k_out() {
    __shared__ float As[64][68];
    __shared__ float Vs[64][72];
    int tid = threadIdx.x;
    int bid = blockIdx.x;
    int w   = bid % WN;
    int bh  = bid / WN;
    int b   = bh >> 2;
    int h   = bh & 3;
#pragma unroll
    for (int it = 0; it < 16; ++it) {
        int i2 = tid + it * 256;
        int rr = i2 >> 6, cc = i2 & 63;
        As[rr][cc] = g_adj[bid * 4096 + i2];
        Vs[rr][cc] = g_v[((b * II + rr) * WN + w) * 256 + h * 64 + cc];
    }
    __syncthreads();
    int warp = tid >> 5, lane = tid & 31;
    int g = lane >> 2, tq = lane & 3;
    int ms = (warp & 3) * 16;
    int nh = (warp >> 2) * 32;
    float acc[4][4];
#pragma unroll
    for (int nt = 0; nt < 4; ++nt)
#pragma unroll
        for (int c = 0; c < 4; ++c) acc[nt][c] = 0.f;
#pragma unroll
    for (int ks = 0; ks < 8; ++ks) {
        int k0 = ks * 8;
        uint32_t ah[4], al[4];
        split_tf32(As[ms + g][k0 + tq],         ah[0], al[0]);
        split_tf32(As[ms + g + 8][k0 + tq],     ah[1], al[1]);
        split_tf32(As[ms + g][k0 + tq + 4],     ah[2], al[2]);
        split_tf32(As[ms + g + 8][k0 + tq + 4], ah[3], al[3]);
#pragma unroll
        for (int nt = 0; nt < 4; ++nt) {
            int n0 = nh + nt * 8 + g;
            uint32_t bhv[2], blv[2];
            split_tf32(Vs[k0 + tq][n0],     bhv[0], blv[0]);
            split_tf32(Vs[k0 + tq + 4][n0], bhv[1], blv[1]);
            mma3(acc[nt], ah, al, bhv, blv);
        }
    }
#pragma unroll
    for (int nt = 0; nt < 4; ++nt) {
        int n0 = nh + nt * 8 + 2 * tq;
        g_o[bid * 4096 + (ms + g) * 64 + n0]         = acc[nt][0];
        g_o[bid * 4096 + (ms + g) * 64 + n0 + 1]     = acc[nt][1];
        g_o[bid * 4096 + (ms + g + 8) * 64 + n0]     = acc[nt][2];
        g_o[bid * 4096 + (ms + g + 8) * 64 + n0 + 1] = acc[nt][3];
    }
}

// ---------------------------------------------------------------------------
// 6. Final assembly: closed form of pad + pair-mean epilogue.
// ---------------------------------------------------------------------------
__global__ __launch_bounds__(256) void k_assemble(float* __restrict__ out) {
    int idx = blockIdx.x * 256 + threadIdx.x;  // exact OUT_ELEMS
    int d = idx & 63;
    int h = (idx >> 6) & 3;
    int p = (idx >> 8) & 63;
    int n = (idx >> 14) & 31;
    int b = idx >> 19;
    int bh = b * 4 + h;
    float val;
    if (p == 0) {
        val = g_o[((bh * WN + 0) * 64 + 2 * n) * 64 + d];
    } else if (p == 63) {
        val = g_o[((bh * WN + 62) * 64 + 2 * n + 1) * 64 + d];
    } else {
        float o0 = g_o[((bh * WN + p) * 64 + 2 * n) * 64 + d];
        float o1 = g_o[((bh * WN + p - 1) * 64 + 2 * n + 1) * 64 + d];
        val = 0.5f * (o0 + o1);
    }
    out[idx] = val;
}

// ---------------------------------------------------------------------------
extern "C" void kernel_launch(void* const* d_in, const int* in_sizes, int n_in,
                              void* d_out, int out_size) {
    const float* x  = (const float*)d_in[0];
    const float* W1 = (const float*)d_in[1];
    const float* b1 = (const float*)d_in[2];
    const float* W2 = (const float*)d_in[3];
    const float* b2 = (const float*)d_in[4];
    const float* Wv = (const float*)d_in[5];
    const float* bv = (const float*)d_in[6];
    float* out = (float*)d_out;

    k_build_wx<<<4096, 256>>>(x);
    k_qk_adj<<<NBHW, 256>>>(W1, b1, W2, b2);
    k_v2<<<M_V / 64, 256>>>(Wv, bv);
    if (out_size > OUT_ELEMS) {
        k_loss_zero<<<1, 1>>>(out);
        k_loss<<<524288 / 256, 256>>>(out);
    }
    k_out<<<NBHW, 256>>>();
    k_assemble<<<OUT_ELEMS / 256, 256>>>(out);
}

// round 9
// speedup vs baseline: 1.0303x; 1.0303x over previous
#include <cuda_runtime.h>
#include <cstdint>

// Problem constants
#define B_  32
#define H_  4
#define L_  2048
#define D_  64
#define N_  32
#define P_  64
#define WN  63          // win_num
#define II  64          // N * win

#define WX_ELEMS 33030144   // B*H*II*WN*D
#define M_V      129024     // B*II*WN
#define NBHW     8064       // B*H*WN
#define OUT_ELEMS 16777216  // B*L*H*D

#define SMEM_V2  86016      // (2*64*36 + 2*32*264) * 4 bytes
#define SMEM_OUT 71680      // (2*64*68 + 2*64*72) * 4 bytes

// Scratch (static device globals — allocation-free per harness rules)
__device__ float g_wx[WX_ELEMS];   // [b][h][i][w][d]
__device__ float g_v [WX_ELEMS];   // [b][i][w][h*64+d]
__device__ float g_adj[WX_ELEMS];  // [b][h][w][i][j]
__device__ float g_o [WX_ELEMS];   // [b][h][w][i][d]

// ---------------------------------------------------------------------------
// tf32 helpers
// ---------------------------------------------------------------------------
__device__ __forceinline__ uint32_t f2tf32(float x) {
    uint32_t r;
    asm("cvt.rna.tf32.f32 %0, %1;" : "=r"(r) : "f"(x));
    return r;
}
__device__ __forceinline__ void split_tf32(float x, uint32_t& hi, uint32_t& lo) {
    asm("cvt.rna.tf32.f32 %0, %1;" : "=r"(hi) : "f"(x));
    float l = x - __uint_as_float(hi);
    asm("cvt.rna.tf32.f32 %0, %1;" : "=r"(lo) : "f"(l));
}
__device__ __forceinline__ void mma8(float* d, const uint32_t* a, const uint32_t* b) {
    asm volatile(
        "mma.sync.aligned.m16n8k8.row.col.f32.tf32.tf32.f32 "
        "{%0,%1,%2,%3}, {%4,%5,%6,%7}, {%8,%9}, {%0,%1,%2,%3};"
        : "+f"(d[0]), "+f"(d[1]), "+f"(d[2]), "+f"(d[3])
        : "r"(a[0]), "r"(a[1]), "r"(a[2]), "r"(a[3]), "r"(b[0]), "r"(b[1]));
}
// 3xTF32: d += a*b with near-fp32 accuracy (lo*hi + hi*lo + hi*hi)
__device__ __forceinline__ void mma3(float* d, const uint32_t* ah, const uint32_t* al,
                                     const uint32_t* bh, const uint32_t* bl) {
    mma8(d, al, bh);
    mma8(d, ah, bl);
    mma8(d, ah, bh);
}

// smem bank swizzle for [64][64] tiles: pc = c ^ ((r&7)*4)
__device__ __forceinline__ int sw(int r, int c) { return c ^ ((r & 7) << 2); }

// ---------------------------------------------------------------------------
// 1. Gather wx, coalesced: one block per (bh, n); stage 64x64 x-tile in smem.
// ---------------------------------------------------------------------------
__global__ __launch_bounds__(256) void k_build_wx(const float* __restrict__ x) {
    __shared__ float xs[64][65];
    int bid = blockIdx.x;          // bh*32 + n, 4096 blocks
    int bh  = bid >> 5;
    int n   = bid & 31;
    int tid = threadIdx.x;
#pragma unroll
    for (int it = 0; it < 16; ++it) {
        int i2 = tid + it * 256;
        int rr = i2 >> 6, cc = i2 & 63;
        xs[rr][cc] = x[(bh * L_ + n * P_ + rr) * D_ + cc];
    }
    __syncthreads();
    float* dst = g_wx + bh * 258048 + n * 8064;
    for (int j = tid; j < 8064; j += 256) {
        int d  = j / 126;
        int r2 = j - d * 126;
        int row = (r2 >> 1) + (r2 & 1);     // w + e
        dst[j] = xs[row][d];
    }
}

// ---------------------------------------------------------------------------
// 2. Fused per (b,h,w): Q=XW1+b1, K=XW2+b2, A=QK^T (all 3xTF32 tensor core),
//    exact top-32 |.| mask, tanh, L1 row-normalize -> g_adj.
//    All tiles [64][64] with XOR bank swizzle.
// ---------------------------------------------------------------------------
__global__ __launch_bounds__(256) void k_qk_adj(const float* __restrict__ W1,
                                                const float* __restrict__ b1,
                                                const float* __restrict__ W2,
                                                const float* __restrict__ b2) {
    __shared__ float Xs[64][64];
    __shared__ float U1[64][64];
    __shared__ float U2[64][64];
    int tid = threadIdx.x;
    int bid = blockIdx.x;
    int w   = bid % WN;
    int bh  = bid / WN;
#pragma unroll
    for (int it = 0; it < 16; ++it) {
        int i2 = tid + it * 256;
        int rr = i2 >> 6, cc = i2 & 63;
        int pc = sw(rr, cc);
        Xs[rr][pc] = g_wx[((bh * II + rr) * WN + w) * D_ + cc];
        U1[rr][pc] = W1[i2];
        U2[rr][pc] = W2[i2];
    }
    __syncthreads();

    int warp = tid >> 5, lane = tid & 31;
    int g = lane >> 2, tq = lane & 3;

    // ---- Phase 1: warps 0-3 -> Q strips, warps 4-7 -> K strips (16x64 each)
    {
        int ms = (warp & 3) * 16;
        bool isK = warp >= 4;
        float (*Wop)[64] = isK ? U2 : U1;
        float acc[8][4];
#pragma unroll
        for (int nt = 0; nt < 8; ++nt)
#pragma unroll
            for (int c = 0; c < 4; ++c) acc[nt][c] = 0.f;
#pragma unroll
        for (int ks = 0; ks < 8; ++ks) {
            int k0 = ks * 8;
            uint32_t ah[4], al[4];
            split_tf32(Xs[ms + g]    [sw(ms + g,     k0 + tq)],     ah[0], al[0]);
            split_tf32(Xs[ms + g + 8][sw(ms + g + 8, k0 + tq)],     ah[1], al[1]);
            split_tf32(Xs[ms + g]    [sw(ms + g,     k0 + tq + 4)], ah[2], al[2]);
            split_tf32(Xs[ms + g + 8][sw(ms + g + 8, k0 + tq + 4)], ah[3], al[3]);
#pragma unroll
            for (int nt = 0; nt < 8; ++nt) {
                uint32_t bhv[2], blv[2];
                split_tf32(Wop[k0 + tq]    [sw(k0 + tq,     nt * 8 + g)], bhv[0], blv[0]);
                split_tf32(Wop[k0 + tq + 4][sw(k0 + tq + 4, nt * 8 + g)], bhv[1], blv[1]);
                mma3(acc[nt], ah, al, bhv, blv);
            }
        }
        __syncthreads();   // all W1/W2 reads done before overwrite
        const float* bias = isK ? b2 : b1;
        float (*Udst)[64] = isK ? U2 : U1;
#pragma unroll
        for (int nt = 0; nt < 8; ++nt) {
            int n0 = nt * 8 + 2 * tq;
            float bb0 = bias[n0], bb1 = bias[n0 + 1];
            Udst[ms + g]    [sw(ms + g,     n0)]     = acc[nt][0] + bb0;
            Udst[ms + g]    [sw(ms + g,     n0 + 1)] = acc[nt][1] + bb1;
            Udst[ms + g + 8][sw(ms + g + 8, n0)]     = acc[nt][2] + bb0;
            Udst[ms + g + 8][sw(ms + g + 8, n0 + 1)] = acc[nt][3] + bb1;
        }
        __syncthreads();
    }

    // ---- Phase 2: A = Q K^T. Warp tile: 16 x 32.
    {
        int ms = (warp & 3) * 16;
        int nh = (warp >> 2) * 32;
        float acc[4][4];
#pragma unroll
        for (int nt = 0; nt < 4; ++nt)
#pragma unroll
            for (int c = 0; c < 4; ++c) acc[nt][c] = 0.f;
#pragma unroll
        for (int ks = 0; ks < 8; ++ks) {
            int k0 = ks * 8;
            uint32_t ah[4], al[4];
            split_tf32(U1[ms + g]    [sw(ms + g,     k0 + tq)],     ah[0], al[0]);
            split_tf32(U1[ms + g + 8][sw(ms + g + 8, k0 + tq)],     ah[1], al[1]);
            split_tf32(U1[ms + g]    [sw(ms + g,     k0 + tq + 4)], ah[2], al[2]);
            split_tf32(U1[ms + g + 8][sw(ms + g + 8, k0 + tq + 4)], ah[3], al[3]);
#pragma unroll
            for (int nt = 0; nt < 4; ++nt) {
                int j0 = nh + nt * 8 + g;
                uint32_t bhv[2], blv[2];
                split_tf32(U2[j0][sw(j0, k0 + tq)],     bhv[0], blv[0]);
                split_tf32(U2[j0][sw(j0, k0 + tq + 4)], bhv[1], blv[1]);
                mma3(acc[nt], ah, al, bhv, blv);
            }
        }
#pragma unroll
        for (int nt = 0; nt < 4; ++nt) {
            int n0 = nh + nt * 8 + 2 * tq;
            Xs[ms + g]    [sw(ms + g,     n0)]     = acc[nt][0];
            Xs[ms + g]    [sw(ms + g,     n0 + 1)] = acc[nt][1];
            Xs[ms + g + 8][sw(ms + g + 8, n0)]     = acc[nt][2];
            Xs[ms + g + 8][sw(ms + g + 8, n0 + 1)] = acc[nt][3];
        }
        __syncthreads();
    }

    // ---- ranking: exact top_k tie semantics; tanh; L1 normalize ----
    int adjbase = bid * 4096;
    for (int r8 = 0; r8 < 8; ++r8) {
        int row = warp * 8 + r8;
        float a1 = Xs[row][sw(row, lane)];
        float a2 = Xs[row][sw(row, lane + 32)];
        float ab1 = fabsf(a1), ab2 = fabsf(a2);
        int c1 = 0, c2 = 0;
#pragma unroll 8
        for (int j = 0; j < 64; ++j) {
            float vj = fabsf(Xs[row][sw(row, j)]);
            c1 += (vj < ab1) || (vj == ab1 && j < lane);
            c2 += (vj < ab2) || (vj == ab2 && j < lane + 32);
        }
        float t1 = (c1 >= 32) ? tanhf(a1) : 0.f;
        float t2 = (c2 >= 32) ? tanhf(a2) : 0.f;
        float s = fabsf(t1) + fabsf(t2);
#pragma unroll
        for (int off = 16; off; off >>= 1) s += __shfl_xor_sync(0xffffffffu, s, off);
        float inv = 1.f / fmaxf(s, 1e-12f);
        g_adj[adjbase + row * 64 + lane]      = t1 * inv;
        g_adj[adjbase + row * 64 + lane + 32] = t2 * inv;
    }
}

// ---------------------------------------------------------------------------
// 3. v = v_in @ Wv + bv  (3xTF32, hi/lo PRE-SPLIT in dynamic smem).
//    64 rows x 256 cols per block; K=256 in 8 chunks of 32.
//    Ah/Al: [64][36] (bank 4g+tq: conflict-free)
//    Bh/Bl: [32][264] (bank 8tq+g: conflict-free)
// ---------------------------------------------------------------------------
__global__ __launch_bounds__(256) void k_v2(const float* __restrict__ Wv,
                                            const float* __restrict__ bv) {
    extern __shared__ uint32_t dyn_v[];
    uint32_t* Ah = dyn_v;              // 64*36
    uint32_t* Al = Ah + 64 * 36;
    uint32_t* Bh = Al + 64 * 36;       // 32*264
    uint32_t* Bl = Bh + 32 * 264;

    int tid  = threadIdx.x;
    int m0   = blockIdx.x * 64;
    int b    = blockIdx.x / 63;
    int rem0 = (blockIdx.x - b * 63) * 64;
    int warp = tid >> 5, lane = tid & 31;
    int g = lane >> 2, tq = lane & 3;
    int ms = (warp & 3) * 16;
    int nh = (warp >> 2) * 128;
    float acc[16][4];
#pragma unroll
    for (int nt = 0; nt < 16; ++nt)
#pragma unroll
        for (int c = 0; c < 4; ++c) acc[nt][c] = 0.f;

    for (int ch = 0; ch < 8; ++ch) {       // global k = ch*32 + kk; h = ch>>1
#pragma unroll
        for (int it = 0; it < 8; ++it) {   // A: 64x32, split at load
            int i2 = tid + it * 256;
            int rr = i2 >> 5, kkc = i2 & 31;
            int rem = rem0 + rr;
            int i  = rem / WN;
            int ww = rem - i * WN;
            float v = g_wx[(((b * H_ + (ch >> 1)) * II + i) * WN + ww) * D_ +
                           (ch & 1) * 32 + kkc];
            uint32_t hi, lo;
            split_tf32(v, hi, lo);
            Ah[rr * 36 + kkc] = hi;
            Al[rr * 36 + kkc] = lo;
        }
#pragma unroll
        for (int it = 0; it < 8; ++it) {   // B: 32x256, split at load
            int i4 = tid + it * 256;
            int r  = i4 >> 6;
            int c  = (i4 & 63) * 4;
            float4 v4 = *(const float4*)&Wv[(ch * 32 + r) * 256 + c];
            uint4 h4, l4;
            split_tf32(v4.x, h4.x, l4.x);
            split_tf32(v4.y, h4.y, l4.y);
            split_tf32(v4.z, h4.z, l4.z);
            split_tf32(v4.w, h4.w, l4.w);
            *(uint4*)&Bh[r * 264 + c] = h4;
            *(uint4*)&Bl[r * 264 + c] = l4;
        }
        __syncthreads();
#pragma unroll
        for (int ks = 0; ks < 4; ++ks) {
            int k0 = ks * 8;
            uint32_t ah[4], al[4];
            ah[0] = Ah[(ms + g) * 36 + k0 + tq];
            ah[1] = Ah[(ms + g + 8) * 36 + k0 + tq];
            ah[2] = Ah[(ms + g) * 36 + k0 + tq + 4];
            ah[3] = Ah[(ms + g + 8) * 36 + k0 + tq + 4];
            al[0] = Al[(ms + g) * 36 + k0 + tq];
            al[1] = Al[(ms + g + 8) * 36 + k0 + tq];
            al[2] = Al[(ms + g) * 36 + k0 + tq + 4];
            al[3] = Al[(ms + g + 8) * 36 + k0 + tq + 4];
#pragma unroll
            for (int nt = 0; nt < 16; ++nt) {
                int n0 = nh + nt * 8 + g;
                uint32_t bhv[2], blv[2];
                bhv[0] = Bh[(k0 + tq) * 264 + n0];
                bhv[1] = Bh[(k0 + tq + 4) * 264 + n0];
                blv[0] = Bl[(k0 + tq) * 264 + n0];
                blv[1] = Bl[(k0 + tq + 4) * 264 + n0];
                mma3(acc[nt], ah, al, bhv, blv);
            }
        }
        __syncthreads();
    }
#pragma unroll
    for (int nt = 0; nt < 16; ++nt) {
        int n0 = nh + nt * 8 + 2 * tq;
        float bb0 = bv[n0], bb1 = bv[n0 + 1];
        g_v[(m0 + ms + g) * 256 + n0]         = acc[nt][0] + bb0;
        g_v[(m0 + ms + g) * 256 + n0 + 1]     = acc[nt][1] + bb1;
        g_v[(m0 + ms + g + 8) * 256 + n0]     = acc[nt][2] + bb0;
        g_v[(m0 + ms + g + 8) * 256 + n0 + 1] = acc[nt][3] + bb1;
    }
}

// ---------------------------------------------------------------------------
// 4. loss = mean_{b,h,i,j} var_w(adj)   (ddof=0, two-pass)
// ---------------------------------------------------------------------------
__global__ void k_loss_zero(float* __restrict__ out) { out[OUT_ELEMS] = 0.f; }

__global__ __launch_bounds__(256) void k_loss(float* __restrict__ out) {
    int idx = blockIdx.x * 256 + threadIdx.x;  // over B*H*64*64 = 524288
    int bh  = idx >> 12;
    int ij  = idx & 4095;
    const float* p = g_adj + bh * (WN * 4096) + ij;
    float s1 = 0.f;
#pragma unroll 7
    for (int w = 0; w < WN; ++w) s1 += p[w * 4096];
    float m = s1 * (1.f / 63.f);
    float s2 = 0.f;
#pragma unroll 7
    for (int w = 0; w < WN; ++w) { float dv = p[w * 4096] - m; s2 += dv * dv; }
    float var = s2 * (1.f / 63.f);
    __shared__ float red[256];
    red[threadIdx.x] = var;
    __syncthreads();
    for (int off = 128; off; off >>= 1) {
        if (threadIdx.x < off) red[threadIdx.x] += red[threadIdx.x + off];
        __syncthreads();
    }
    if (threadIdx.x == 0) atomicAdd(out + OUT_ELEMS, red[0] * (1.f / 524288.f));
}

// ---------------------------------------------------------------------------
// 5. Per (b,h,w): O = A_w @ V_w (3xTF32, hi/lo PRE-SPLIT in dynamic smem).
//    Ah/Al: [64][68] (bank 4g+tq: free); Vh/Vl: [64][72] (bank 8tq+g: free)
// ---------------------------------------------------------------------------
__global__ __launch_bounds__(256) void k_out() {
    extern __shared__ uint32_t dyn_o[];
    uint32_t* Ah = dyn_o;               // 64*68
    uint32_t* Al = Ah + 64 * 68;
    uint32_t* Vh = Al + 64 * 68;        // 64*72
    uint32_t* Vl = Vh + 64 * 72;

    int tid = threadIdx.x;
    int bid = blockIdx.x;
    int w   = bid % WN;
    int bh  = bid / WN;
    int b   = bh >> 2;
    int h   = bh & 3;
#pragma unroll
    for (int it = 0; it < 16; ++it) {
        int i2 = tid + it * 256;
        int rr = i2 >> 6, cc = i2 & 63;
        uint32_t hi, lo;
        split_tf32(g_adj[bid * 4096 + i2], hi, lo);
        Ah[rr * 68 + cc] = hi;
        Al[rr * 68 + cc] = lo;
        split_tf32(g_v[((b * II + rr) * WN + w) * 256 + h * 64 + cc], hi, lo);
        Vh[rr * 72 + cc] = hi;
        Vl[rr * 72 + cc] = lo;
    }
    __syncthreads();
    int warp = tid >> 5, lane = tid & 31;
    int g = lane >> 2, tq = lane & 3;
    int ms = (warp & 3) * 16;
    int nh = (warp >> 2) * 32;
    float acc[4][4];
#pragma unroll
    for (int nt = 0; nt < 4; ++nt)
#pragma unroll
        for (int c = 0; c < 4; ++c) acc[nt][c] = 0.f;
#pragma unroll
    for (int ks = 0; ks < 8; ++ks) {
        int k0 = ks * 8;
        uint32_t ah[4], al[4];
        ah[0] = Ah[(ms + g) * 68 + k0 + tq];
        ah[1] = Ah[(ms + g + 8) * 68 + k0 + tq];
        ah[2] = Ah[(ms + g) * 68 + k0 + tq + 4];
        ah[3] = Ah[(ms + g + 8) * 68 + k0 + tq + 4];
        al[0] = Al[(ms + g) * 68 + k0 + tq];
        al[1] = Al[(ms + g + 8) * 68 + k0 + tq];
        al[2] = Al[(ms + g) * 68 + k0 + tq + 4];
        al[3] = Al[(ms + g + 8) * 68 + k0 + tq + 4];
#pragma unroll
        for (int nt = 0; nt < 4; ++nt) {
            int n0 = nh + nt * 8 + g;
            uint32_t bhv[2], blv[2];
            bhv[0] = Vh[(k0 + tq) * 72 + n0];
            bhv[1] = Vh[(k0 + tq + 4) * 72 + n0];
            blv[0] = Vl[(k0 + tq) * 72 + n0];
            blv[1] = Vl[(k0 + tq + 4) * 72 + n0];
            mma3(acc[nt], ah, al, bhv, blv);
        }
    }
#pragma unroll
    for (int nt = 0; nt < 4; ++nt) {
        int n0 = nh + nt * 8 + 2 * tq;
        g_o[bid * 4096 + (ms + g) * 64 + n0]         = acc[nt][0];
        g_o[bid * 4096 + (ms + g) * 64 + n0 + 1]     = acc[nt][1];
        g_o[bid * 4096 + (ms + g + 8) * 64 + n0]     = acc[nt][2];
        g_o[bid * 4096 + (ms + g + 8) * 64 + n0 + 1] = acc[nt][3];
    }
}

// ---------------------------------------------------------------------------
// 6. Final assembly: closed form of pad + pair-mean epilogue.
// ---------------------------------------------------------------------------
__global__ __launch_bounds__(256) void k_assemble(float* __restrict__ out) {
    int idx = blockIdx.x * 256 + threadIdx.x;  // exact OUT_ELEMS
    int d = idx & 63;
    int h = (idx >> 6) & 3;
    int p = (idx >> 8) & 63;
    int n = (idx >> 14) & 31;
    int b = idx >> 19;
    int bh = b * 4 + h;
    float val;
    if (p == 0) {
        val = g_o[((bh * WN + 0) * 64 + 2 * n) * 64 + d];
    } else if (p == 63) {
        val = g_o[((bh * WN + 62) * 64 + 2 * n + 1) * 64 + d];
    } else {
        float o0 = g_o[((bh * WN + p) * 64 + 2 * n) * 64 + d];
        float o1 = g_o[((bh * WN + p - 1) * 64 + 2 * n + 1) * 64 + d];
        val = 0.5f * (o0 + o1);
    }
    out[idx] = val;
}

// ---------------------------------------------------------------------------
extern "C" void kernel_launch(void* const* d_in, const int* in_sizes, int n_in,
                              void* d_out, int out_size) {
    const float* x  = (const float*)d_in[0];
    const float* W1 = (const float*)d_in[1];
    const float* b1 = (const float*)d_in[2];
    const float* W2 = (const float*)d_in[3];
    const float* b2 = (const float*)d_in[4];
    const float* Wv = (const float*)d_in[5];
    const float* bv = (const float*)d_in[6];
    float* out = (float*)d_out;

    cudaFuncSetAttribute(k_v2,  cudaFuncAttributeMaxDynamicSharedMemorySize, SMEM_V2);
    cudaFuncSetAttribute(k_out, cudaFuncAttributeMaxDynamicSharedMemorySize, SMEM_OUT);

    k_build_wx<<<4096, 256>>>(x);
    k_qk_adj<<<NBHW, 256>>>(W1, b1, W2, b2);
    k_v2<<<M_V / 64, 256, SMEM_V2>>>(Wv, bv);
    if (out_size > OUT_ELEMS) {
        k_loss_zero<<<1, 1>>>(out);
        k_loss<<<524288 / 256, 256>>>(out);
    }
    k_out<<<NBHW, 256, SMEM_OUT>>>();
    k_assemble<<<OUT_ELEMS / 256, 256>>>(out);
}

// round 10
// speedup vs baseline: 1.1419x; 1.1083x over previous
#include <cuda_runtime.h>
#include <cstdint>

// Problem constants
#define B_  32
#define H_  4
#define L_  2048
#define D_  64
#define N_  32
#define P_  64
#define WN  63          // win_num
#define II  64          // N * win

#define WX_ELEMS 33030144   // B*H*II*WN*D
#define M_V      129024     // B*II*WN
#define NBHW     8064       // B*H*WN
#define OUT_ELEMS 16777216  // B*L*H*D

#define SMEM_OUT 71680      // (2*64*68 + 2*64*72) * 4 bytes

// Scratch (static device globals — allocation-free per harness rules)
__device__ float g_wx[WX_ELEMS];   // [b][h][i][w][d]
__device__ float g_v [WX_ELEMS];   // [b][i][w][h*64+d]
__device__ float g_adj[WX_ELEMS];  // [b][h][w][i][j]
__device__ float g_o [WX_ELEMS];   // [b][h][w][i][d]

// ---------------------------------------------------------------------------
// tf32 helpers
// ---------------------------------------------------------------------------
__device__ __forceinline__ uint32_t f2tf32(float x) {
    uint32_t r;
    asm("cvt.rna.tf32.f32 %0, %1;" : "=r"(r) : "f"(x));
    return r;
}
__device__ __forceinline__ void split_tf32(float x, uint32_t& hi, uint32_t& lo) {
    asm("cvt.rna.tf32.f32 %0, %1;" : "=r"(hi) : "f"(x));
    float l = x - __uint_as_float(hi);
    asm("cvt.rna.tf32.f32 %0, %1;" : "=r"(lo) : "f"(l));
}
__device__ __forceinline__ void mma8(float* d, const uint32_t* a, const uint32_t* b) {
    asm volatile(
        "mma.sync.aligned.m16n8k8.row.col.f32.tf32.tf32.f32 "
        "{%0,%1,%2,%3}, {%4,%5,%6,%7}, {%8,%9}, {%0,%1,%2,%3};"
        : "+f"(d[0]), "+f"(d[1]), "+f"(d[2]), "+f"(d[3])
        : "r"(a[0]), "r"(a[1]), "r"(a[2]), "r"(a[3]), "r"(b[0]), "r"(b[1]));
}
// 3xTF32: d += a*b with near-fp32 accuracy (lo*hi + hi*lo + hi*hi)
__device__ __forceinline__ void mma3(float* d, const uint32_t* ah, const uint32_t* al,
                                     const uint32_t* bh, const uint32_t* bl) {
    mma8(d, al, bh);
    mma8(d, ah, bl);
    mma8(d, ah, bh);
}

// smem bank swizzle for [64][64] tiles: pc = c ^ ((r&7)*4)
__device__ __forceinline__ int sw(int r, int c) { return c ^ ((r & 7) << 2); }

// ---------------------------------------------------------------------------
// 1. Gather wx, coalesced: one block per (bh, n); stage 64x64 x-tile in smem.
// ---------------------------------------------------------------------------
__global__ __launch_bounds__(256) void k_build_wx(const float* __restrict__ x) {
    __shared__ float xs[64][65];
    int bid = blockIdx.x;          // bh*32 + n, 4096 blocks
    int bh  = bid >> 5;
    int n   = bid & 31;
    int tid = threadIdx.x;
#pragma unroll
    for (int it = 0; it < 16; ++it) {
        int i2 = tid + it * 256;
        int rr = i2 >> 6, cc = i2 & 63;
        xs[rr][cc] = x[(bh * L_ + n * P_ + rr) * D_ + cc];
    }
    __syncthreads();
    float* dst = g_wx + bh * 258048 + n * 8064;
    for (int j = tid; j < 8064; j += 256) {
        int d  = j / 126;
        int r2 = j - d * 126;
        int row = (r2 >> 1) + (r2 & 1);     // w + e
        dst[j] = xs[row][d];
    }
}

// ---------------------------------------------------------------------------
// 2. Fused per (b,h,w): Q=XW1+b1, K=XW2+b2, A=QK^T (all 3xTF32 tensor core),
//    exact top-32 |.| mask, tanh, L1 row-normalize -> g_adj.
//    All tiles [64][64] with XOR bank swizzle.
// ---------------------------------------------------------------------------
__global__ __launch_bounds__(256) void k_qk_adj(const float* __restrict__ W1,
                                                const float* __restrict__ b1,
                                                const float* __restrict__ W2,
                                                const float* __restrict__ b2) {
    __shared__ float Xs[64][64];
    __shared__ float U1[64][64];
    __shared__ float U2[64][64];
    int tid = threadIdx.x;
    int bid = blockIdx.x;
    int w   = bid % WN;
    int bh  = bid / WN;
#pragma unroll
    for (int it = 0; it < 16; ++it) {
        int i2 = tid + it * 256;
        int rr = i2 >> 6, cc = i2 & 63;
        int pc = sw(rr, cc);
        Xs[rr][pc] = g_wx[((bh * II + rr) * WN + w) * D_ + cc];
        U1[rr][pc] = W1[i2];
        U2[rr][pc] = W2[i2];
    }
    __syncthreads();

    int warp = tid >> 5, lane = tid & 31;
    int g = lane >> 2, tq = lane & 3;

    // ---- Phase 1: warps 0-3 -> Q strips, warps 4-7 -> K strips (16x64 each)
    {
        int ms = (warp & 3) * 16;
        bool isK = warp >= 4;
        float (*Wop)[64] = isK ? U2 : U1;
        float acc[8][4];
#pragma unroll
        for (int nt = 0; nt < 8; ++nt)
#pragma unroll
            for (int c = 0; c < 4; ++c) acc[nt][c] = 0.f;
#pragma unroll
        for (int ks = 0; ks < 8; ++ks) {
            int k0 = ks * 8;
            uint32_t ah[4], al[4];
            split_tf32(Xs[ms + g]    [sw(ms + g,     k0 + tq)],     ah[0], al[0]);
            split_tf32(Xs[ms + g + 8][sw(ms + g + 8, k0 + tq)],     ah[1], al[1]);
            split_tf32(Xs[ms + g]    [sw(ms + g,     k0 + tq + 4)], ah[2], al[2]);
            split_tf32(Xs[ms + g + 8][sw(ms + g + 8, k0 + tq + 4)], ah[3], al[3]);
#pragma unroll
            for (int nt = 0; nt < 8; ++nt) {
                uint32_t bhv[2], blv[2];
                split_tf32(Wop[k0 + tq]    [sw(k0 + tq,     nt * 8 + g)], bhv[0], blv[0]);
                split_tf32(Wop[k0 + tq + 4][sw(k0 + tq + 4, nt * 8 + g)], bhv[1], blv[1]);
                mma3(acc[nt], ah, al, bhv, blv);
            }
        }
        __syncthreads();   // all W1/W2 reads done before overwrite
        const float* bias = isK ? b2 : b1;
        float (*Udst)[64] = isK ? U2 : U1;
#pragma unroll
        for (int nt = 0; nt < 8; ++nt) {
            int n0 = nt * 8 + 2 * tq;
            float bb0 = bias[n0], bb1 = bias[n0 + 1];
            Udst[ms + g]    [sw(ms + g,     n0)]     = acc[nt][0] + bb0;
            Udst[ms + g]    [sw(ms + g,     n0 + 1)] = acc[nt][1] + bb1;
            Udst[ms + g + 8][sw(ms + g + 8, n0)]     = acc[nt][2] + bb0;
            Udst[ms + g + 8][sw(ms + g + 8, n0 + 1)] = acc[nt][3] + bb1;
        }
        __syncthreads();
    }

    // ---- Phase 2: A = Q K^T. Warp tile: 16 x 32.
    {
        int ms = (warp & 3) * 16;
        int nh = (warp >> 2) * 32;
        float acc[4][4];
#pragma unroll
        for (int nt = 0; nt < 4; ++nt)
#pragma unroll
            for (int c = 0; c < 4; ++c) acc[nt][c] = 0.f;
#pragma unroll
        for (int ks = 0; ks < 8; ++ks) {
            int k0 = ks * 8;
            uint32_t ah[4], al[4];
            split_tf32(U1[ms + g]    [sw(ms + g,     k0 + tq)],     ah[0], al[0]);
            split_tf32(U1[ms + g + 8][sw(ms + g + 8, k0 + tq)],     ah[1], al[1]);
            split_tf32(U1[ms + g]    [sw(ms + g,     k0 + tq + 4)], ah[2], al[2]);
            split_tf32(U1[ms + g + 8][sw(ms + g + 8, k0 + tq + 4)], ah[3], al[3]);
#pragma unroll
            for (int nt = 0; nt < 4; ++nt) {
                int j0 = nh + nt * 8 + g;
                uint32_t bhv[2], blv[2];
                split_tf32(U2[j0][sw(j0, k0 + tq)],     bhv[0], blv[0]);
                split_tf32(U2[j0][sw(j0, k0 + tq + 4)], bhv[1], blv[1]);
                mma3(acc[nt], ah, al, bhv, blv);
            }
        }
#pragma unroll
        for (int nt = 0; nt < 4; ++nt) {
            int n0 = nh + nt * 8 + 2 * tq;
            Xs[ms + g]    [sw(ms + g,     n0)]     = acc[nt][0];
            Xs[ms + g]    [sw(ms + g,     n0 + 1)] = acc[nt][1];
            Xs[ms + g + 8][sw(ms + g + 8, n0)]     = acc[nt][2];
            Xs[ms + g + 8][sw(ms + g + 8, n0 + 1)] = acc[nt][3];
        }
        __syncthreads();
    }

    // ---- ranking: exact top_k tie semantics; tanh; L1 normalize ----
    int adjbase = bid * 4096;
    for (int r8 = 0; r8 < 8; ++r8) {
        int row = warp * 8 + r8;
        float a1 = Xs[row][sw(row, lane)];
        float a2 = Xs[row][sw(row, lane + 32)];
        float ab1 = fabsf(a1), ab2 = fabsf(a2);
        int c1 = 0, c2 = 0;
#pragma unroll 8
        for (int j = 0; j < 64; ++j) {
            float vj = fabsf(Xs[row][sw(row, j)]);
            c1 += (vj < ab1) || (vj == ab1 && j < lane);
            c2 += (vj < ab2) || (vj == ab2 && j < lane + 32);
        }
        float t1 = (c1 >= 32) ? tanhf(a1) : 0.f;
        float t2 = (c2 >= 32) ? tanhf(a2) : 0.f;
        float s = fabsf(t1) + fabsf(t2);
#pragma unroll
        for (int off = 16; off; off >>= 1) s += __shfl_xor_sync(0xffffffffu, s, off);
        float inv = 1.f / fmaxf(s, 1e-12f);
        g_adj[adjbase + row * 64 + lane]      = t1 * inv;
        g_adj[adjbase + row * 64 + lane + 32] = t2 * inv;
    }
}

// ---------------------------------------------------------------------------
// 3. v = v_in @ Wv + bv  (1xTF32). 64 rows x 256 cols per block.
//    A pre-converted to tf32 at store, stride 36 (bank 4g+tq: conflict-free).
//    B pre-converted to tf32, stride 264 (bank 8tq+g: conflict-free).
//    Static smem: (64*36 + 32*264)*4 = 43008 B.
// ---------------------------------------------------------------------------
__global__ __launch_bounds__(256) void k_v2(const float* __restrict__ Wv,
                                            const float* __restrict__ bv) {
    __shared__ uint32_t As[64 * 36];
    __shared__ __align__(16) uint32_t Bs[32 * 264];
    int tid  = threadIdx.x;
    int m0   = blockIdx.x * 64;
    int b    = blockIdx.x / 63;
    int rem0 = (blockIdx.x - b * 63) * 64;
    int warp = tid >> 5, lane = tid & 31;
    int g = lane >> 2, tq = lane & 3;
    int ms = (warp & 3) * 16;
    int nh = (warp >> 2) * 128;
    float acc[16][4];
#pragma unroll
    for (int nt = 0; nt < 16; ++nt)
#pragma unroll
        for (int c = 0; c < 4; ++c) acc[nt][c] = 0.f;

    for (int ch = 0; ch < 8; ++ch) {       // global k = ch*32 + kk; h = ch>>1
#pragma unroll
        for (int it = 0; it < 8; ++it) {   // A: 64x32, cvt tf32 at store
            int i2 = tid + it * 256;
            int rr = i2 >> 5, kkc = i2 & 31;
            int rem = rem0 + rr;
            int i  = rem / WN;
            int ww = rem - i * WN;
            As[rr * 36 + kkc] = f2tf32(
                g_wx[(((b * H_ + (ch >> 1)) * II + i) * WN + ww) * D_ +
                     (ch & 1) * 32 + kkc]);
        }
#pragma unroll
        for (int it = 0; it < 8; ++it) {   // B: 32x256, cvt tf32 at store
            int i4 = tid + it * 256;
            int r  = i4 >> 6;
            int c  = (i4 & 63) * 4;
            float4 v4 = *(const float4*)&Wv[(ch * 32 + r) * 256 + c];
            uint4 t;
            t.x = f2tf32(v4.x); t.y = f2tf32(v4.y);
            t.z = f2tf32(v4.z); t.w = f2tf32(v4.w);
            *(uint4*)&Bs[r * 264 + c] = t;
        }
        __syncthreads();
#pragma unroll
        for (int ks = 0; ks < 4; ++ks) {
            int k0 = ks * 8;
            uint32_t a[4];
            a[0] = As[(ms + g) * 36 + k0 + tq];
            a[1] = As[(ms + g + 8) * 36 + k0 + tq];
            a[2] = As[(ms + g) * 36 + k0 + tq + 4];
            a[3] = As[(ms + g + 8) * 36 + k0 + tq + 4];
#pragma unroll
            for (int nt = 0; nt < 16; ++nt) {
                int n0 = nh + nt * 8 + g;
                uint32_t bb[2];
                bb[0] = Bs[(k0 + tq) * 264 + n0];
                bb[1] = Bs[(k0 + tq + 4) * 264 + n0];
                mma8(acc[nt], a, bb);
            }
        }
        __syncthreads();
    }
#pragma unroll
    for (int nt = 0; nt < 16; ++nt) {
        int n0 = nh + nt * 8 + 2 * tq;
        float bb0 = bv[n0], bb1 = bv[n0 + 1];
        g_v[(m0 + ms + g) * 256 + n0]         = acc[nt][0] + bb0;
        g_v[(m0 + ms + g) * 256 + n0 + 1]     = acc[nt][1] + bb1;
        g_v[(m0 + ms + g + 8) * 256 + n0]     = acc[nt][2] + bb0;
        g_v[(m0 + ms + g + 8) * 256 + n0 + 1] = acc[nt][3] + bb1;
    }
}

// ---------------------------------------------------------------------------
// 4. loss = mean_{b,h,i,j} var_w(adj)   (ddof=0, two-pass)
// ---------------------------------------------------------------------------
__global__ void k_loss_zero(float* __restrict__ out) { out[OUT_ELEMS] = 0.f; }

__global__ __launch_bounds__(256) void k_loss(float* __restrict__ out) {
    int idx = blockIdx.x * 256 + threadIdx.x;  // over B*H*64*64 = 524288
    int bh  = idx >> 12;
    int ij  = idx & 4095;
    const float* p = g_adj + bh * (WN * 4096) + ij;
    float s1 = 0.f;
#pragma unroll 7
    for (int w = 0; w < WN; ++w) s1 += p[w * 4096];
    float m = s1 * (1.f / 63.f);
    float s2 = 0.f;
#pragma unroll 7
    for (int w = 0; w < WN; ++w) { float dv = p[w * 4096] - m; s2 += dv * dv; }
    float var = s2 * (1.f / 63.f);
    __shared__ float red[256];
    red[threadIdx.x] = var;
    __syncthreads();
    for (int off = 128; off; off >>= 1) {
        if (threadIdx.x < off) red[threadIdx.x] += red[threadIdx.x + off];
        __syncthreads();
    }
    if (threadIdx.x == 0) atomicAdd(out + OUT_ELEMS, red[0] * (1.f / 524288.f));
}

// ---------------------------------------------------------------------------
// 5. Per (b,h,w): O = A_w @ V_w (3xTF32, hi/lo PRE-SPLIT in dynamic smem).
//    Ah/Al: [64][68] (bank 4g+tq: free); Vh/Vl: [64][72] (bank 8tq+g: free)
// ---------------------------------------------------------------------------
__global__ __launch_bounds__(256) void k_out() {
    extern __shared__ uint32_t dyn_o[];
    uint32_t* Ah = dyn_o;               // 64*68
    uint32_t* Al = Ah + 64 * 68;
    uint32_t* Vh = Al + 64 * 68;        // 64*72
    uint32_t* Vl = Vh + 64 * 72;

    int tid = threadIdx.x;
    int bid = blockIdx.x;
    int w   = bid % WN;
    int bh  = bid / WN;
    int b   = bh >> 2;
    int h   = bh & 3;
#pragma unroll
    for (int it = 0; it < 16; ++it) {
        int i2 = tid + it * 256;
        int rr = i2 >> 6, cc = i2 & 63;
        uint32_t hi, lo;
        split_tf32(g_adj[bid * 4096 + i2], hi, lo);
        Ah[rr * 68 + cc] = hi;
        Al[rr * 68 + cc] = lo;
        split_tf32(g_v[((b * II + rr) * WN + w) * 256 + h * 64 + cc], hi, lo);
        Vh[rr * 72 + cc] = hi;
        Vl[rr * 72 + cc] = lo;
    }
    __syncthreads();
    int warp = tid >> 5, lane = tid & 31;
    int g = lane >> 2, tq = lane & 3;
    int ms = (warp & 3) * 16;
    int nh = (warp >> 2) * 32;
    float acc[4][4];
#pragma unroll
    for (int nt = 0; nt < 4; ++nt)
#pragma unroll
        for (int c = 0; c < 4; ++c) acc[nt][c] = 0.f;
#pragma unroll
    for (int ks = 0; ks < 8; ++ks) {
        int k0 = ks * 8;
        uint32_t ah[4], al[4];
        ah[0] = Ah[(ms + g) * 68 + k0 + tq];
        ah[1] = Ah[(ms + g + 8) * 68 + k0 + tq];
        ah[2] = Ah[(ms + g) * 68 + k0 + tq + 4];
        ah[3] = Ah[(ms + g + 8) * 68 + k0 + tq + 4];
        al[0] = Al[(ms + g) * 68 + k0 + tq];
        al[1] = Al[(ms + g + 8) * 68 + k0 + tq];
        al[2] = Al[(ms + g) * 68 + k0 + tq + 4];
        al[3] = Al[(ms + g + 8) * 68 + k0 + tq + 4];
#pragma unroll
        for (int nt = 0; nt < 4; ++nt) {
            int n0 = nh + nt * 8 + g;
            uint32_t bhv[2], blv[2];
            bhv[0] = Vh[(k0 + tq) * 72 + n0];
            bhv[1] = Vh[(k0 + tq + 4) * 72 + n0];
            blv[0] = Vl[(k0 + tq) * 72 + n0];
            blv[1] = Vl[(k0 + tq + 4) * 72 + n0];
            mma3(acc[nt], ah, al, bhv, blv);
        }
    }
#pragma unroll
    for (int nt = 0; nt < 4; ++nt) {
        int n0 = nh + nt * 8 + 2 * tq;
        g_o[bid * 4096 + (ms + g) * 64 + n0]         = acc[nt][0];
        g_o[bid * 4096 + (ms + g) * 64 + n0 + 1]     = acc[nt][1];
        g_o[bid * 4096 + (ms + g + 8) * 64 + n0]     = acc[nt][2];
        g_o[bid * 4096 + (ms + g + 8) * 64 + n0 + 1] = acc[nt][3];
    }
}

// ---------------------------------------------------------------------------
// 6. Final assembly: closed form of pad + pair-mean epilogue.
// ---------------------------------------------------------------------------
__global__ __launch_bounds__(256) void k_assemble(float* __restrict__ out) {
    int idx = blockIdx.x * 256 + threadIdx.x;  // exact OUT_ELEMS
    int d = idx & 63;
    int h = (idx >> 6) & 3;
    int p = (idx >> 8) & 63;
    int n = (idx >> 14) & 31;
    int b = idx >> 19;
    int bh = b * 4 + h;
    float val;
    if (p == 0) {
        val = g_o[((bh * WN + 0) * 64 + 2 * n) * 64 + d];
    } else if (p == 63) {
        val = g_o[((bh * WN + 62) * 64 + 2 * n + 1) * 64 + d];
    } else {
        float o0 = g_o[((bh * WN + p) * 64 + 2 * n) * 64 + d];
        float o1 = g_o[((bh * WN + p - 1) * 64 + 2 * n + 1) * 64 + d];
        val = 0.5f * (o0 + o1);
    }
    out[idx] = val;
}

// ---------------------------------------------------------------------------
extern "C" void kernel_launch(void* const* d_in, const int* in_sizes, int n_in,
                              void* d_out, int out_size) {
    const float* x  = (const float*)d_in[0];
    const float* W1 = (const float*)d_in[1];
    const float* b1 = (const float*)d_in[2];
    const float* W2 = (const float*)d_in[3];
    const float* b2 = (const float*)d_in[4];
    const float* Wv = (const float*)d_in[5];
    const float* bv = (const float*)d_in[6];
    float* out = (float*)d_out;

    cudaFuncSetAttribute(k_out, cudaFuncAttributeMaxDynamicSharedMemorySize, SMEM_OUT);

    k_build_wx<<<4096, 256>>>(x);
    k_qk_adj<<<NBHW, 256>>>(W1, b1, W2, b2);
    k_v2<<<M_V / 64, 256>>>(Wv, bv);
    if (out_size > OUT_ELEMS) {
        k_loss_zero<<<1, 1>>>(out);
        k_loss<<<524288 / 256, 256>>>(out);
    }
    k_out<<<NBHW, 256, SMEM_OUT>>>();
    k_assemble<<<OUT_ELEMS / 256, 256>>>(out);
}

// round 11
// speedup vs baseline: 1.1737x; 1.0278x over previous
#include <cuda_runtime.h>
#include <cstdint>

// Problem constants
#define B_  32
#define H_  4
#define L_  2048
#define D_  64
#define N_  32
#define P_  64
#define WN  63          // win_num
#define II  64          // N * win

#define WX_ELEMS 33030144   // B*H*II*WN*D
#define M_V      129024     // B*II*WN
#define NBHW     8064       // B*H*WN
#define OUT_ELEMS 16777216  // B*L*H*D

// Scratch (static device globals — allocation-free per harness rules)
__device__ float g_wx[WX_ELEMS];   // [b][h][i][w][d]
__device__ float g_v [WX_ELEMS];   // [b][i][w][h*64+d]
__device__ float g_adj[WX_ELEMS];  // [b][h][w][i][j]
__device__ float g_o [WX_ELEMS];   // [b][h][w][i][d]

// ---------------------------------------------------------------------------
// tf32 helpers
// ---------------------------------------------------------------------------
__device__ __forceinline__ uint32_t f2tf32(float x) {
    uint32_t r;
    asm("cvt.rna.tf32.f32 %0, %1;" : "=r"(r) : "f"(x));
    return r;
}
__device__ __forceinline__ void split_tf32(float x, uint32_t& hi, uint32_t& lo) {
    asm("cvt.rna.tf32.f32 %0, %1;" : "=r"(hi) : "f"(x));
    float l = x - __uint_as_float(hi);
    asm("cvt.rna.tf32.f32 %0, %1;" : "=r"(lo) : "f"(l));
}
__device__ __forceinline__ void mma8(float* d, const uint32_t* a, const uint32_t* b) {
    asm volatile(
        "mma.sync.aligned.m16n8k8.row.col.f32.tf32.tf32.f32 "
        "{%0,%1,%2,%3}, {%4,%5,%6,%7}, {%8,%9}, {%0,%1,%2,%3};"
        : "+f"(d[0]), "+f"(d[1]), "+f"(d[2]), "+f"(d[3])
        : "r"(a[0]), "r"(a[1]), "r"(a[2]), "r"(a[3]), "r"(b[0]), "r"(b[1]));
}
// 3xTF32: d += a*b with near-fp32 accuracy (lo*hi + hi*lo + hi*hi)
__device__ __forceinline__ void mma3(float* d, const uint32_t* ah, const uint32_t* al,
                                     const uint32_t* bh, const uint32_t* bl) {
    mma8(d, al, bh);
    mma8(d, ah, bl);
    mma8(d, ah, bh);
}

// smem bank swizzle for [64][64] tiles: pc = c ^ ((r&7)*4)
__device__ __forceinline__ int sw(int r, int c) { return c ^ ((r & 7) << 2); }

// ---------------------------------------------------------------------------
// 1. Gather wx, coalesced: one block per (bh, n); stage 64x64 x-tile in smem.
// ---------------------------------------------------------------------------
__global__ __launch_bounds__(256) void k_build_wx(const float* __restrict__ x) {
    __shared__ float xs[64][65];
    int bid = blockIdx.x;          // bh*32 + n, 4096 blocks
    int bh  = bid >> 5;
    int n   = bid & 31;
    int tid = threadIdx.x;
#pragma unroll
    for (int it = 0; it < 16; ++it) {
        int i2 = tid + it * 256;
        int rr = i2 >> 6, cc = i2 & 63;
        xs[rr][cc] = x[(bh * L_ + n * P_ + rr) * D_ + cc];
    }
    __syncthreads();
    float* dst = g_wx + bh * 258048 + n * 8064;
    for (int j = tid; j < 8064; j += 256) {
        int d  = j / 126;
        int r2 = j - d * 126;
        int row = (r2 >> 1) + (r2 & 1);     // w + e
        dst[j] = xs[row][d];
    }
}

// ---------------------------------------------------------------------------
// 2. Fused per (b,h,w): Q=XW1+b1, K=XW2+b2, A=QK^T (all 3xTF32 tensor core),
//    exact top-32 |.| mask, tanh, L1 row-normalize -> g_adj.
//    All tiles [64][64] with XOR bank swizzle.
// ---------------------------------------------------------------------------
__global__ __launch_bounds__(256) void k_qk_adj(const float* __restrict__ W1,
                                                const float* __restrict__ b1,
                                                const float* __restrict__ W2,
                                                const float* __restrict__ b2) {
    __shared__ float Xs[64][64];
    __shared__ float U1[64][64];
    __shared__ float U2[64][64];
    int tid = threadIdx.x;
    int bid = blockIdx.x;
    int w   = bid % WN;
    int bh  = bid / WN;
#pragma unroll
    for (int it = 0; it < 16; ++it) {
        int i2 = tid + it * 256;
        int rr = i2 >> 6, cc = i2 & 63;
        int pc = sw(rr, cc);
        Xs[rr][pc] = g_wx[((bh * II + rr) * WN + w) * D_ + cc];
        U1[rr][pc] = W1[i2];
        U2[rr][pc] = W2[i2];
    }
    __syncthreads();

    int warp = tid >> 5, lane = tid & 31;
    int g = lane >> 2, tq = lane & 3;

    // ---- Phase 1: warps 0-3 -> Q strips, warps 4-7 -> K strips (16x64 each)
    {
        int ms = (warp & 3) * 16;
        bool isK = warp >= 4;
        float (*Wop)[64] = isK ? U2 : U1;
        float acc[8][4];
#pragma unroll
        for (int nt = 0; nt < 8; ++nt)
#pragma unroll
            for (int c = 0; c < 4; ++c) acc[nt][c] = 0.f;
#pragma unroll
        for (int ks = 0; ks < 8; ++ks) {
            int k0 = ks * 8;
            uint32_t ah[4], al[4];
            split_tf32(Xs[ms + g]    [sw(ms + g,     k0 + tq)],     ah[0], al[0]);
            split_tf32(Xs[ms + g + 8][sw(ms + g + 8, k0 + tq)],     ah[1], al[1]);
            split_tf32(Xs[ms + g]    [sw(ms + g,     k0 + tq + 4)], ah[2], al[2]);
            split_tf32(Xs[ms + g + 8][sw(ms + g + 8, k0 + tq + 4)], ah[3], al[3]);
#pragma unroll
            for (int nt = 0; nt < 8; ++nt) {
                uint32_t bhv[2], blv[2];
                split_tf32(Wop[k0 + tq]    [sw(k0 + tq,     nt * 8 + g)], bhv[0], blv[0]);
                split_tf32(Wop[k0 + tq + 4][sw(k0 + tq + 4, nt * 8 + g)], bhv[1], blv[1]);
                mma3(acc[nt], ah, al, bhv, blv);
            }
        }
        __syncthreads();   // all W1/W2 reads done before overwrite
        const float* bias = isK ? b2 : b1;
        float (*Udst)[64] = isK ? U2 : U1;
#pragma unroll
        for (int nt = 0; nt < 8; ++nt) {
            int n0 = nt * 8 + 2 * tq;
            float bb0 = bias[n0], bb1 = bias[n0 + 1];
            Udst[ms + g]    [sw(ms + g,     n0)]     = acc[nt][0] + bb0;
            Udst[ms + g]    [sw(ms + g,     n0 + 1)] = acc[nt][1] + bb1;
            Udst[ms + g + 8][sw(ms + g + 8, n0)]     = acc[nt][2] + bb0;
            Udst[ms + g + 8][sw(ms + g + 8, n0 + 1)] = acc[nt][3] + bb1;
        }
        __syncthreads();
    }

    // ---- Phase 2: A = Q K^T. Warp tile: 16 x 32.
    {
        int ms = (warp & 3) * 16;
        int nh = (warp >> 2) * 32;
        float acc[4][4];
#pragma unroll
        for (int nt = 0; nt < 4; ++nt)
#pragma unroll
            for (int c = 0; c < 4; ++c) acc[nt][c] = 0.f;
#pragma unroll
        for (int ks = 0; ks < 8; ++ks) {
            int k0 = ks * 8;
            uint32_t ah[4], al[4];
            split_tf32(U1[ms + g]    [sw(ms + g,     k0 + tq)],     ah[0], al[0]);
            split_tf32(U1[ms + g + 8][sw(ms + g + 8, k0 + tq)],     ah[1], al[1]);
            split_tf32(U1[ms + g]    [sw(ms + g,     k0 + tq + 4)], ah[2], al[2]);
            split_tf32(U1[ms + g + 8][sw(ms + g + 8, k0 + tq + 4)], ah[3], al[3]);
#pragma unroll
            for (int nt = 0; nt < 4; ++nt) {
                int j0 = nh + nt * 8 + g;
                uint32_t bhv[2], blv[2];
                split_tf32(U2[j0][sw(j0, k0 + tq)],     bhv[0], blv[0]);
                split_tf32(U2[j0][sw(j0, k0 + tq + 4)], bhv[1], blv[1]);
                mma3(acc[nt], ah, al, bhv, blv);
            }
        }
#pragma unroll
        for (int nt = 0; nt < 4; ++nt) {
            int n0 = nh + nt * 8 + 2 * tq;
            Xs[ms + g]    [sw(ms + g,     n0)]     = acc[nt][0];
            Xs[ms + g]    [sw(ms + g,     n0 + 1)] = acc[nt][1];
            Xs[ms + g + 8][sw(ms + g + 8, n0)]     = acc[nt][2];
            Xs[ms + g + 8][sw(ms + g + 8, n0 + 1)] = acc[nt][3];
        }
        __syncthreads();
    }

    // ---- ranking: exact top_k tie semantics; tanh; L1 normalize ----
    int adjbase = bid * 4096;
    for (int r8 = 0; r8 < 8; ++r8) {
        int row = warp * 8 + r8;
        float a1 = Xs[row][sw(row, lane)];
        float a2 = Xs[row][sw(row, lane + 32)];
        float ab1 = fabsf(a1), ab2 = fabsf(a2);
        int c1 = 0, c2 = 0;
#pragma unroll 8
        for (int j = 0; j < 64; ++j) {
            float vj = fabsf(Xs[row][sw(row, j)]);
            c1 += (vj < ab1) || (vj == ab1 && j < lane);
            c2 += (vj < ab2) || (vj == ab2 && j < lane + 32);
        }
        float t1 = (c1 >= 32) ? tanhf(a1) : 0.f;
        float t2 = (c2 >= 32) ? tanhf(a2) : 0.f;
        float s = fabsf(t1) + fabsf(t2);
#pragma unroll
        for (int off = 16; off; off >>= 1) s += __shfl_xor_sync(0xffffffffu, s, off);
        float inv = 1.f / fmaxf(s, 1e-12f);
        g_adj[adjbase + row * 64 + lane]      = t1 * inv;
        g_adj[adjbase + row * 64 + lane + 32] = t2 * inv;
    }
}

// ---------------------------------------------------------------------------
// 3. v = v_in @ Wv + bv  (1xTF32). 64 rows x 256 cols per block.
//    A pre-converted to tf32 at store, stride 36 (bank 4g+tq: conflict-free).
//    B pre-converted to tf32, stride 264 (bank 8tq+g: conflict-free).
// ---------------------------------------------------------------------------
__global__ __launch_bounds__(256) void k_v2(const float* __restrict__ Wv,
                                            const float* __restrict__ bv) {
    __shared__ uint32_t As[64 * 36];
    __shared__ __align__(16) uint32_t Bs[32 * 264];
    int tid  = threadIdx.x;
    int m0   = blockIdx.x * 64;
    int b    = blockIdx.x / 63;
    int rem0 = (blockIdx.x - b * 63) * 64;
    int warp = tid >> 5, lane = tid & 31;
    int g = lane >> 2, tq = lane & 3;
    int ms = (warp & 3) * 16;
    int nh = (warp >> 2) * 128;
    float acc[16][4];
#pragma unroll
    for (int nt = 0; nt < 16; ++nt)
#pragma unroll
        for (int c = 0; c < 4; ++c) acc[nt][c] = 0.f;

    for (int ch = 0; ch < 8; ++ch) {       // global k = ch*32 + kk; h = ch>>1
#pragma unroll
        for (int it = 0; it < 8; ++it) {   // A: 64x32, cvt tf32 at store
            int i2 = tid + it * 256;
            int rr = i2 >> 5, kkc = i2 & 31;
            int rem = rem0 + rr;
            int i  = rem / WN;
            int ww = rem - i * WN;
            As[rr * 36 + kkc] = f2tf32(
                g_wx[(((b * H_ + (ch >> 1)) * II + i) * WN + ww) * D_ +
                     (ch & 1) * 32 + kkc]);
        }
#pragma unroll
        for (int it = 0; it < 8; ++it) {   // B: 32x256, cvt tf32 at store
            int i4 = tid + it * 256;
            int r  = i4 >> 6;
            int c  = (i4 & 63) * 4;
            float4 v4 = *(const float4*)&Wv[(ch * 32 + r) * 256 + c];
            uint4 t;
            t.x = f2tf32(v4.x); t.y = f2tf32(v4.y);
            t.z = f2tf32(v4.z); t.w = f2tf32(v4.w);
            *(uint4*)&Bs[r * 264 + c] = t;
        }
        __syncthreads();
#pragma unroll
        for (int ks = 0; ks < 4; ++ks) {
            int k0 = ks * 8;
            uint32_t a[4];
            a[0] = As[(ms + g) * 36 + k0 + tq];
            a[1] = As[(ms + g + 8) * 36 + k0 + tq];
            a[2] = As[(ms + g) * 36 + k0 + tq + 4];
            a[3] = As[(ms + g + 8) * 36 + k0 + tq + 4];
#pragma unroll
            for (int nt = 0; nt < 16; ++nt) {
                int n0 = nh + nt * 8 + g;
                uint32_t bb[2];
                bb[0] = Bs[(k0 + tq) * 264 + n0];
                bb[1] = Bs[(k0 + tq + 4) * 264 + n0];
                mma8(acc[nt], a, bb);
            }
        }
        __syncthreads();
    }
#pragma unroll
    for (int nt = 0; nt < 16; ++nt) {
        int n0 = nh + nt * 8 + 2 * tq;
        float bb0 = bv[n0], bb1 = bv[n0 + 1];
        g_v[(m0 + ms + g) * 256 + n0]         = acc[nt][0] + bb0;
        g_v[(m0 + ms + g) * 256 + n0 + 1]     = acc[nt][1] + bb1;
        g_v[(m0 + ms + g + 8) * 256 + n0]     = acc[nt][2] + bb0;
        g_v[(m0 + ms + g + 8) * 256 + n0 + 1] = acc[nt][3] + bb1;
    }
}

// ---------------------------------------------------------------------------
// 4. loss = mean_{b,h,i,j} var_w(adj)   (ddof=0, two-pass)
// ---------------------------------------------------------------------------
__global__ void k_loss_zero(float* __restrict__ out) { out[OUT_ELEMS] = 0.f; }

__global__ __launch_bounds__(256) void k_loss(float* __restrict__ out) {
    int idx = blockIdx.x * 256 + threadIdx.x;  // over B*H*64*64 = 524288
    int bh  = idx >> 12;
    int ij  = idx & 4095;
    const float* p = g_adj + bh * (WN * 4096) + ij;
    float s1 = 0.f;
#pragma unroll 7
    for (int w = 0; w < WN; ++w) s1 += p[w * 4096];
    float m = s1 * (1.f / 63.f);
    float s2 = 0.f;
#pragma unroll 7
    for (int w = 0; w < WN; ++w) { float dv = p[w * 4096] - m; s2 += dv * dv; }
    float var = s2 * (1.f / 63.f);
    __shared__ float red[256];
    red[threadIdx.x] = var;
    __syncthreads();
    for (int off = 128; off; off >>= 1) {
        if (threadIdx.x < off) red[threadIdx.x] += red[threadIdx.x + off];
        __syncthreads();
    }
    if (threadIdx.x == 0) atomicAdd(out + OUT_ELEMS, red[0] * (1.f / 524288.f));
}

// ---------------------------------------------------------------------------
// 5. Per (b,h,w): O = A_w @ V_w (1xTF32, pre-converted, conflict-free).
//    As: stride 68 (bank 4g+tq: free); Vs: stride 72 (bank 8tq+g: free).
//    Static smem (64*68 + 64*72)*4 = 35840 B -> full occupancy.
// ---------------------------------------------------------------------------
__global__ __launch_bounds__(256) void k_out() {
    __shared__ uint32_t As[64 * 68];
    __shared__ uint32_t Vs[64 * 72];
    int tid = threadIdx.x;
    int bid = blockIdx.x;
    int w   = bid % WN;
    int bh  = bid / WN;
    int b   = bh >> 2;
    int h   = bh & 3;
#pragma unroll
    for (int it = 0; it < 16; ++it) {
        int i2 = tid + it * 256;
        int rr = i2 >> 6, cc = i2 & 63;
        As[rr * 68 + cc] = f2tf32(g_adj[bid * 4096 + i2]);
        Vs[rr * 72 + cc] = f2tf32(g_v[((b * II + rr) * WN + w) * 256 + h * 64 + cc]);
    }
    __syncthreads();
    int warp = tid >> 5, lane = tid & 31;
    int g = lane >> 2, tq = lane & 3;
    int ms = (warp & 3) * 16;
    int nh = (warp >> 2) * 32;
    float acc[4][4];
#pragma unroll
    for (int nt = 0; nt < 4; ++nt)
#pragma unroll
        for (int c = 0; c < 4; ++c) acc[nt][c] = 0.f;
#pragma unroll
    for (int ks = 0; ks < 8; ++ks) {
        int k0 = ks * 8;
        uint32_t a[4];
        a[0] = As[(ms + g) * 68 + k0 + tq];
        a[1] = As[(ms + g + 8) * 68 + k0 + tq];
        a[2] = As[(ms + g) * 68 + k0 + tq + 4];
        a[3] = As[(ms + g + 8) * 68 + k0 + tq + 4];
#pragma unroll
        for (int nt = 0; nt < 4; ++nt) {
            int n0 = nh + nt * 8 + g;
            uint32_t bb[2];
            bb[0] = Vs[(k0 + tq) * 72 + n0];
            bb[1] = Vs[(k0 + tq + 4) * 72 + n0];
            mma8(acc[nt], a, bb);
        }
    }
#pragma unroll
    for (int nt = 0; nt < 4; ++nt) {
        int n0 = nh + nt * 8 + 2 * tq;
        g_o[bid * 4096 + (ms + g) * 64 + n0]         = acc[nt][0];
        g_o[bid * 4096 + (ms + g) * 64 + n0 + 1]     = acc[nt][1];
        g_o[bid * 4096 + (ms + g + 8) * 64 + n0]     = acc[nt][2];
        g_o[bid * 4096 + (ms + g + 8) * 64 + n0 + 1] = acc[nt][3];
    }
}

// ---------------------------------------------------------------------------
// 6. Final assembly: closed form of pad + pair-mean epilogue.
// ---------------------------------------------------------------------------
__global__ __launch_bounds__(256) void k_assemble(float* __restrict__ out) {
    int idx = blockIdx.x * 256 + threadIdx.x;  // exact OUT_ELEMS
    int d = idx & 63;
    int h = (idx >> 6) & 3;
    int p = (idx >> 8) & 63;
    int n = (idx >> 14) & 31;
    int b = idx >> 19;
    int bh = b * 4 + h;
    float val;
    if (p == 0) {
        val = g_o[((bh * WN + 0) * 64 + 2 * n) * 64 + d];
    } else if (p == 63) {
        val = g_o[((bh * WN + 62) * 64 + 2 * n + 1) * 64 + d];
    } else {
        float o0 = g_o[((bh * WN + p) * 64 + 2 * n) * 64 + d];
        float o1 = g_o[((bh * WN + p - 1) * 64 + 2 * n + 1) * 64 + d];
        val = 0.5f * (o0 + o1);
    }
    out[idx] = val;
}

// ---------------------------------------------------------------------------
// Launch order note: the ncu capture profiles the 4th launch in this list
// (empirical across R3/R6/R7/R9). k_qk_adj is deliberately placed 4th so the
// next round's profile shows the presumed-hot kernel. Dependencies respected:
// v2 needs g_wx; qk_adj needs g_wx; loss needs g_adj; out needs g_adj+g_v.
// ---------------------------------------------------------------------------
extern "C" void kernel_launch(void* const* d_in, const int* in_sizes, int n_in,
                              void* d_out, int out_size) {
    const float* x  = (const float*)d_in[0];
    const float* W1 = (const float*)d_in[1];
    const float* b1 = (const float*)d_in[2];
    const float* W2 = (const float*)d_in[3];
    const float* b2 = (const float*)d_in[4];
    const float* Wv = (const float*)d_in[5];
    const float* bv = (const float*)d_in[6];
    float* out = (float*)d_out;

    k_build_wx<<<4096, 256>>>(x);
    k_v2<<<M_V / 64, 256>>>(Wv, bv);
    if (out_size > OUT_ELEMS) {
        k_loss_zero<<<1, 1>>>(out);
        k_qk_adj<<<NBHW, 256>>>(W1, b1, W2, b2);
        k_loss<<<524288 / 256, 256>>>(out);
    } else {
        k_qk_adj<<<NBHW, 256>>>(W1, b1, W2, b2);
    }
    k_out<<<NBHW, 256>>>();
    k_assemble<<<OUT_ELEMS / 256, 256>>>(out);
}

// round 12
// speedup vs baseline: 1.4782x; 1.2595x over previous
#include <cuda_runtime.h>
#include <cstdint>

// Problem constants
#define B_  32
#define H_  4
#define L_  2048
#define D_  64
#define N_  32
#define P_  64
#define WN  63          // win_num
#define II  64          // N * win

#define WX_ELEMS 33030144   // B*H*II*WN*D
#define M_V      129024     // B*II*WN
#define NBHW     8064       // B*H*WN
#define OUT_ELEMS 16777216  // B*L*H*D

#define QK_S     72                       // padded row stride (conflict-free)
#define SMEM_QK  (6 * 64 * QK_S * 4)      // 110592 B dynamic for k_qk_adj

// Scratch (static device globals — allocation-free per harness rules)
__device__ float g_wx[WX_ELEMS];   // [b][h][i][w][d]
__device__ float g_v [WX_ELEMS];   // [b][i][w][h*64+d]
__device__ float g_adj[WX_ELEMS];  // [b][h][w][i][j]
__device__ float g_o [WX_ELEMS];   // [b][h][w][i][d]
__device__ uint32_t g_w1h[4096], g_w1l[4096], g_w2h[4096], g_w2l[4096];

// ---------------------------------------------------------------------------
// tf32 helpers
// ---------------------------------------------------------------------------
__device__ __forceinline__ uint32_t f2tf32(float x) {
    uint32_t r;
    asm("cvt.rna.tf32.f32 %0, %1;" : "=r"(r) : "f"(x));
    return r;
}
__device__ __forceinline__ void split_tf32(float x, uint32_t& hi, uint32_t& lo) {
    asm("cvt.rna.tf32.f32 %0, %1;" : "=r"(hi) : "f"(x));
    float l = x - __uint_as_float(hi);
    asm("cvt.rna.tf32.f32 %0, %1;" : "=r"(lo) : "f"(l));
}
__device__ __forceinline__ void mma8(float* d, const uint32_t* a, const uint32_t* b) {
    asm volatile(
        "mma.sync.aligned.m16n8k8.row.col.f32.tf32.tf32.f32 "
        "{%0,%1,%2,%3}, {%4,%5,%6,%7}, {%8,%9}, {%0,%1,%2,%3};"
        : "+f"(d[0]), "+f"(d[1]), "+f"(d[2]), "+f"(d[3])
        : "r"(a[0]), "r"(a[1]), "r"(a[2]), "r"(a[3]), "r"(b[0]), "r"(b[1]));
}
// 3xTF32: d += a*b with near-fp32 accuracy (lo*hi + hi*lo + hi*hi)
__device__ __forceinline__ void mma3(float* d, const uint32_t* ah, const uint32_t* al,
                                     const uint32_t* bh, const uint32_t* bl) {
    mma8(d, al, bh);
    mma8(d, ah, bl);
    mma8(d, ah, bh);
}

// ---------------------------------------------------------------------------
// 0. Pre-split W1/W2 into tf32 hi/lo (runs once per launch, trivial cost)
// ---------------------------------------------------------------------------
__global__ __launch_bounds__(256) void k_split_w(const float* __restrict__ W1,
                                                 const float* __restrict__ W2) {
    int i = blockIdx.x * 256 + threadIdx.x;   // 4096 exact
    split_tf32(W1[i], g_w1h[i], g_w1l[i]);
    split_tf32(W2[i], g_w2h[i], g_w2l[i]);
}

// ---------------------------------------------------------------------------
// 1. Gather wx, coalesced: one block per (bh, n); stage 64x64 x-tile in smem.
// ---------------------------------------------------------------------------
__global__ __launch_bounds__(256) void k_build_wx(const float* __restrict__ x) {
    __shared__ float xs[64][65];
    int bid = blockIdx.x;          // bh*32 + n, 4096 blocks
    int bh  = bid >> 5;
    int n   = bid & 31;
    int tid = threadIdx.x;
#pragma unroll
    for (int it = 0; it < 16; ++it) {
        int i2 = tid + it * 256;
        int rr = i2 >> 6, cc = i2 & 63;
        xs[rr][cc] = x[(bh * L_ + n * P_ + rr) * D_ + cc];
    }
    __syncthreads();
    float* dst = g_wx + bh * 258048 + n * 8064;
    for (int j = tid; j < 8064; j += 256) {
        int d  = j / 126;
        int r2 = j - d * 126;
        int row = (r2 >> 1) + (r2 & 1);     // w + e
        dst[j] = xs[row][d];
    }
}

// ---------------------------------------------------------------------------
// 2. Fused per (b,h,w): Q=XW1+b1, K=XW2+b2, A=QK^T (3xTF32, all splits hoisted
//    out of the mainloops), top-32 |.| keep mask (count-based, tie-break
//    dropped: exact bitwise ties have ~0 probability and are within the
//    accepted flip-error floor), tanh, L1 row-normalize -> g_adj.
//    6 padded stride-72 smem buffers; every fragment pattern conflict-free.
// ---------------------------------------------------------------------------
__global__ __launch_bounds__(256) void k_qk_adj(const float* __restrict__ b1,
                                                const float* __restrict__ b2) {
    extern __shared__ uint32_t dyn_q[];
    uint32_t* Xh  = dyn_q;               // X hi       -> later A (fp32)
    uint32_t* Xl  = Xh  + 64 * QK_S;     // X lo
    uint32_t* U1h = Xl  + 64 * QK_S;     // W1 hi      -> later Q hi
    uint32_t* U1l = U1h + 64 * QK_S;     // W1 lo      -> later Q lo
    uint32_t* U2h = U1l + 64 * QK_S;     // W2 hi      -> later K hi
    uint32_t* U2l = U2h + 64 * QK_S;     // W2 lo      -> later K lo

    int tid = threadIdx.x;
    int bid = blockIdx.x;
    int w   = bid % WN;
    int bh  = bid / WN;
#pragma unroll
    for (int it = 0; it < 16; ++it) {
        int i2 = tid + it * 256;
        int rr = i2 >> 6, cc = i2 & 63;
        int p  = rr * QK_S + cc;
        uint32_t hi, lo;
        split_tf32(g_wx[((bh * II + rr) * WN + w) * D_ + cc], hi, lo);
        Xh[p] = hi;  Xl[p] = lo;
        U1h[p] = g_w1h[i2];  U1l[p] = g_w1l[i2];
        U2h[p] = g_w2h[i2];  U2l[p] = g_w2l[i2];
    }
    __syncthreads();

    int warp = tid >> 5, lane = tid & 31;
    int g = lane >> 2, tq = lane & 3;
    int ms = (warp & 3) * 16;
    int r0 = (ms + g) * QK_S, r1 = (ms + g + 8) * QK_S;

    // ---- Phase 1: warps 0-3 -> Q strips, warps 4-7 -> K strips (16x64 each)
    {
        bool isK = warp >= 4;
        const uint32_t* Wh = isK ? U2h : U1h;
        const uint32_t* Wl = isK ? U2l : U1l;
        float acc[8][4];
#pragma unroll
        for (int nt = 0; nt < 8; ++nt)
#pragma unroll
            for (int c = 0; c < 4; ++c) acc[nt][c] = 0.f;
#pragma unroll
        for (int ks = 0; ks < 8; ++ks) {
            int k0 = ks * 8;
            uint32_t ah[4], al[4];
            ah[0] = Xh[r0 + k0 + tq];     ah[1] = Xh[r1 + k0 + tq];
            ah[2] = Xh[r0 + k0 + tq + 4]; ah[3] = Xh[r1 + k0 + tq + 4];
            al[0] = Xl[r0 + k0 + tq];     al[1] = Xl[r1 + k0 + tq];
            al[2] = Xl[r0 + k0 + tq + 4]; al[3] = Xl[r1 + k0 + tq + 4];
            int b0 = (k0 + tq) * QK_S, b4 = (k0 + tq + 4) * QK_S;
#pragma unroll
            for (int nt = 0; nt < 8; ++nt) {
                int cb = nt * 8 + g;
                uint32_t bhv[2], blv[2];
                bhv[0] = Wh[b0 + cb]; bhv[1] = Wh[b4 + cb];
                blv[0] = Wl[b0 + cb]; blv[1] = Wl[b4 + cb];
                mma3(acc[nt], ah, al, bhv, blv);
            }
        }
        __syncthreads();   // all weight reads done before overwrite
        const float* bias = isK ? b2 : b1;
        uint32_t* Dh = isK ? U2h : U1h;
        uint32_t* Dl = isK ? U2l : U1l;
#pragma unroll
        for (int nt = 0; nt < 8; ++nt) {
            int n0 = nt * 8 + 2 * tq;
            float bb0 = bias[n0], bb1 = bias[n0 + 1];
            uint32_t hi, lo;
            split_tf32(acc[nt][0] + bb0, hi, lo); Dh[r0 + n0]     = hi; Dl[r0 + n0]     = lo;
            split_tf32(acc[nt][1] + bb1, hi, lo); Dh[r0 + n0 + 1] = hi; Dl[r0 + n0 + 1] = lo;
            split_tf32(acc[nt][2] + bb0, hi, lo); Dh[r1 + n0]     = hi; Dl[r1 + n0]     = lo;
            split_tf32(acc[nt][3] + bb1, hi, lo); Dh[r1 + n0 + 1] = hi; Dl[r1 + n0 + 1] = lo;
        }
        __syncthreads();
    }

    // ---- Phase 2: A = Q K^T (Q in U1h/l, K in U2h/l). Warp tile: 16 x 32.
    float* Abuf = (float*)Xh;            // reuse X-hi buffer for fp32 A
    {
        int nh = (warp >> 2) * 32;
        float acc[4][4];
#pragma unroll
        for (int nt = 0; nt < 4; ++nt)
#pragma unroll
            for (int c = 0; c < 4; ++c) acc[nt][c] = 0.f;
#pragma unroll
        for (int ks = 0; ks < 8; ++ks) {
            int k0 = ks * 8;
            uint32_t ah[4], al[4];
            ah[0] = U1h[r0 + k0 + tq];     ah[1] = U1h[r1 + k0 + tq];
            ah[2] = U1h[r0 + k0 + tq + 4]; ah[3] = U1h[r1 + k0 + tq + 4];
            al[0] = U1l[r0 + k0 + tq];     al[1] = U1l[r1 + k0 + tq];
            al[2] = U1l[r0 + k0 + tq + 4]; al[3] = U1l[r1 + k0 + tq + 4];
#pragma unroll
            for (int nt = 0; nt < 4; ++nt) {
                int j0 = (nh + nt * 8 + g) * QK_S;
                uint32_t bhv[2], blv[2];
                bhv[0] = U2h[j0 + k0 + tq]; bhv[1] = U2h[j0 + k0 + tq + 4];
                blv[0] = U2l[j0 + k0 + tq]; blv[1] = U2l[j0 + k0 + tq + 4];
                mma3(acc[nt], ah, al, bhv, blv);
            }
        }
#pragma unroll
        for (int nt = 0; nt < 4; ++nt) {
            int n0 = nh + nt * 8 + 2 * tq;
            Abuf[r0 + n0]     = acc[nt][0];
            Abuf[r0 + n0 + 1] = acc[nt][1];
            Abuf[r1 + n0]     = acc[nt][2];
            Abuf[r1 + n0 + 1] = acc[nt][3];
        }
        __syncthreads();
    }

    // ---- ranking: shuffle-based top-32 count; tanh; L1 normalize ----
    int adjbase = bid * 4096;
    for (int r8 = 0; r8 < 8; ++r8) {
        int row = warp * 8 + r8;
        float a1 = Abuf[row * QK_S + lane];
        float a2 = Abuf[row * QK_S + lane + 32];
        float ab1 = fabsf(a1), ab2 = fabsf(a2);
        int c1 = 0, c2 = 0;
#pragma unroll
        for (int j = 0; j < 32; ++j) {
            float v = __shfl_sync(0xffffffffu, ab1, j);
            c1 += v < ab1;
            c2 += v < ab2;
        }
#pragma unroll
        for (int j = 0; j < 32; ++j) {
            float v = __shfl_sync(0xffffffffu, ab2, j);
            c1 += v < ab1;
            c2 += v < ab2;
        }
        float t1 = (c1 >= 32) ? tanhf(a1) : 0.f;
        float t2 = (c2 >= 32) ? tanhf(a2) : 0.f;
        float s = fabsf(t1) + fabsf(t2);
#pragma unroll
        for (int off = 16; off; off >>= 1) s += __shfl_xor_sync(0xffffffffu, s, off);
        float inv = 1.f / fmaxf(s, 1e-12f);
        g_adj[adjbase + row * 64 + lane]      = t1 * inv;
        g_adj[adjbase + row * 64 + lane + 32] = t2 * inv;
    }
}

// ---------------------------------------------------------------------------
// 3. v = v_in @ Wv + bv  (1xTF32). 64 rows x 256 cols per block.
//    A pre-converted to tf32 at store, stride 36 (bank 4g+tq: conflict-free).
//    B pre-converted to tf32, stride 264 (bank 8tq+g: conflict-free).
// ---------------------------------------------------------------------------
__global__ __launch_bounds__(256) void k_v2(const float* __restrict__ Wv,
                                            const float* __restrict__ bv) {
    __shared__ uint32_t As[64 * 36];
    __shared__ __align__(16) uint32_t Bs[32 * 264];
    int tid  = threadIdx.x;
    int m0   = blockIdx.x * 64;
    int b    = blockIdx.x / 63;
    int rem0 = (blockIdx.x - b * 63) * 64;
    int warp = tid >> 5, lane = tid & 31;
    int g = lane >> 2, tq = lane & 3;
    int ms = (warp & 3) * 16;
    int nh = (warp >> 2) * 128;
    float acc[16][4];
#pragma unroll
    for (int nt = 0; nt < 16; ++nt)
#pragma unroll
        for (int c = 0; c < 4; ++c) acc[nt][c] = 0.f;

    for (int ch = 0; ch < 8; ++ch) {       // global k = ch*32 + kk; h = ch>>1
#pragma unroll
        for (int it = 0; it < 8; ++it) {   // A: 64x32, cvt tf32 at store
            int i2 = tid + it * 256;
            int rr = i2 >> 5, kkc = i2 & 31;
            int rem = rem0 + rr;
            int i  = rem / WN;
            int ww = rem - i * WN;
            As[rr * 36 + kkc] = f2tf32(
                g_wx[(((b * H_ + (ch >> 1)) * II + i) * WN + ww) * D_ +
                     (ch & 1) * 32 + kkc]);
        }
#pragma unroll
        for (int it = 0; it < 8; ++it) {   // B: 32x256, cvt tf32 at store
            int i4 = tid + it * 256;
            int r  = i4 >> 6;
            int c  = (i4 & 63) * 4;
            float4 v4 = *(const float4*)&Wv[(ch * 32 + r) * 256 + c];
            uint4 t;
            t.x = f2tf32(v4.x); t.y = f2tf32(v4.y);
            t.z = f2tf32(v4.z); t.w = f2tf32(v4.w);
            *(uint4*)&Bs[r * 264 + c] = t;
        }
        __syncthreads();
#pragma unroll
        for (int ks = 0; ks < 4; ++ks) {
            int k0 = ks * 8;
            uint32_t a[4];
            a[0] = As[(ms + g) * 36 + k0 + tq];
            a[1] = As[(ms + g + 8) * 36 + k0 + tq];
            a[2] = As[(ms + g) * 36 + k0 + tq + 4];
            a[3] = As[(ms + g + 8) * 36 + k0 + tq + 4];
#pragma unroll
            for (int nt = 0; nt < 16; ++nt) {
                int n0 = nh + nt * 8 + g;
                uint32_t bb[2];
                bb[0] = Bs[(k0 + tq) * 264 + n0];
                bb[1] = Bs[(k0 + tq + 4) * 264 + n0];
                mma8(acc[nt], a, bb);
            }
        }
        __syncthreads();
    }
#pragma unroll
    for (int nt = 0; nt < 16; ++nt) {
        int n0 = nh + nt * 8 + 2 * tq;
        float bb0 = bv[n0], bb1 = bv[n0 + 1];
        g_v[(m0 + ms + g) * 256 + n0]         = acc[nt][0] + bb0;
        g_v[(m0 + ms + g) * 256 + n0 + 1]     = acc[nt][1] + bb1;
        g_v[(m0 + ms + g + 8) * 256 + n0]     = acc[nt][2] + bb0;
        g_v[(m0 + ms + g + 8) * 256 + n0 + 1] = acc[nt][3] + bb1;
    }
}

// ---------------------------------------------------------------------------
// 4. loss = mean_{b,h,i,j} var_w(adj)   (ddof=0, two-pass)
// ---------------------------------------------------------------------------
__global__ void k_loss_zero(float* __restrict__ out) { out[OUT_ELEMS] = 0.f; }

__global__ __launch_bounds__(256) void k_loss(float* __restrict__ out) {
    int idx = blockIdx.x * 256 + threadIdx.x;  // over B*H*64*64 = 524288
    int bh  = idx >> 12;
    int ij  = idx & 4095;
    const float* p = g_adj + bh * (WN * 4096) + ij;
    float s1 = 0.f;
#pragma unroll 7
    for (int w = 0; w < WN; ++w) s1 += p[w * 4096];
    float m = s1 * (1.f / 63.f);
    float s2 = 0.f;
#pragma unroll 7
    for (int w = 0; w < WN; ++w) { float dv = p[w * 4096] - m; s2 += dv * dv; }
    float var = s2 * (1.f / 63.f);
    __shared__ float red[256];
    red[threadIdx.x] = var;
    __syncthreads();
    for (int off = 128; off; off >>= 1) {
        if (threadIdx.x < off) red[threadIdx.x] += red[threadIdx.x + off];
        __syncthreads();
    }
    if (threadIdx.x == 0) atomicAdd(out + OUT_ELEMS, red[0] * (1.f / 524288.f));
}

// ---------------------------------------------------------------------------
// 5. Per (b,h,w): O = A_w @ V_w (1xTF32, pre-converted, conflict-free).
//    As: stride 68 (bank 4g+tq: free); Vs: stride 72 (bank 8tq+g: free).
// ---------------------------------------------------------------------------
__global__ __launch_bounds__(256) void k_out() {
    __shared__ uint32_t As[64 * 68];
    __shared__ uint32_t Vs[64 * 72];
    int tid = threadIdx.x;
    int bid = blockIdx.x;
    int w   = bid % WN;
    int bh  = bid / WN;
    int b   = bh >> 2;
    int h   = bh & 3;
#pragma unroll
    for (int it = 0; it < 16; ++it) {
        int i2 = tid + it * 256;
        int rr = i2 >> 6, cc = i2 & 63;
        As[rr * 68 + cc] = f2tf32(g_adj[bid * 4096 + i2]);
        Vs[rr * 72 + cc] = f2tf32(g_v[((b * II + rr) * WN + w) * 256 + h * 64 + cc]);
    }
    __syncthreads();
    int warp = tid >> 5, lane = tid & 31;
    int g = lane >> 2, tq = lane & 3;
    int ms = (warp & 3) * 16;
    int nh = (warp >> 2) * 32;
    float acc[4][4];
#pragma unroll
    for (int nt = 0; nt < 4; ++nt)
#pragma unroll
        for (int c = 0; c < 4; ++c) acc[nt][c] = 0.f;
#pragma unroll
    for (int ks = 0; ks < 8; ++ks) {
        int k0 = ks * 8;
        uint32_t a[4];
        a[0] = As[(ms + g) * 68 + k0 + tq];
        a[1] = As[(ms + g + 8) * 68 + k0 + tq];
        a[2] = As[(ms + g) * 68 + k0 + tq + 4];
        a[3] = As[(ms + g + 8) * 68 + k0 + tq + 4];
#pragma unroll
        for (int nt = 0; nt < 4; ++nt) {
            int n0 = nh + nt * 8 + g;
            uint32_t bb[2];
            bb[0] = Vs[(k0 + tq) * 72 + n0];
            bb[1] = Vs[(k0 + tq + 4) * 72 + n0];
            mma8(acc[nt], a, bb);
        }
    }
#pragma unroll
    for (int nt = 0; nt < 4; ++nt) {
        int n0 = nh + nt * 8 + 2 * tq;
        g_o[bid * 4096 + (ms + g) * 64 + n0]         = acc[nt][0];
        g_o[bid * 4096 + (ms + g) * 64 + n0 + 1]     = acc[nt][1];
        g_o[bid * 4096 + (ms + g + 8) * 64 + n0]     = acc[nt][2];
        g_o[bid * 4096 + (ms + g + 8) * 64 + n0 + 1] = acc[nt][3];
    }
}

// ---------------------------------------------------------------------------
// 6. Final assembly: closed form of pad + pair-mean epilogue.
// ---------------------------------------------------------------------------
__global__ __launch_bounds__(256) void k_assemble(float* __restrict__ out) {
    int idx = blockIdx.x * 256 + threadIdx.x;  // exact OUT_ELEMS
    int d = idx & 63;
    int h = (idx >> 6) & 3;
    int p = (idx >> 8) & 63;
    int n = (idx >> 14) & 31;
    int b = idx >> 19;
    int bh = b * 4 + h;
    float val;
    if (p == 0) {
        val = g_o[((bh * WN + 0) * 64 + 2 * n) * 64 + d];
    } else if (p == 63) {
        val = g_o[((bh * WN + 62) * 64 + 2 * n + 1) * 64 + d];
    } else {
        float o0 = g_o[((bh * WN + p) * 64 + 2 * n) * 64 + d];
        float o1 = g_o[((bh * WN + p - 1) * 64 + 2 * n + 1) * 64 + d];
        val = 0.5f * (o0 + o1);
    }
    out[idx] = val;
}

// ---------------------------------------------------------------------------
// Launch order: k_qk_adj kept in slot 4 (ncu profiles the 4th launch).
// Deps: split_w before qk_adj; build_wx before v2/qk_adj; qk_adj before
// loss/out; v2 before out; out before assemble.
// ---------------------------------------------------------------------------
extern "C" void kernel_launch(void* const* d_in, const int* in_sizes, int n_in,
                              void* d_out, int out_size) {
    const float* x  = (const float*)d_in[0];
    const float* W1 = (const float*)d_in[1];
    const float* b1 = (const float*)d_in[2];
    const float* W2 = (const float*)d_in[3];
    const float* b2 = (const float*)d_in[4];
    const float* Wv = (const float*)d_in[5];
    const float* bv = (const float*)d_in[6];
    float* out = (float*)d_out;

    cudaFuncSetAttribute(k_qk_adj, cudaFuncAttributeMaxDynamicSharedMemorySize,
                         SMEM_QK);

    k_build_wx<<<4096, 256>>>(x);
    k_v2<<<M_V / 64, 256>>>(Wv, bv);
    k_split_w<<<16, 256>>>(W1, W2);
    k_qk_adj<<<NBHW, 256, SMEM_QK>>>(b1, b2);
    if (out_size > OUT_ELEMS) {
        k_loss_zero<<<1, 1>>>(out);
        k_loss<<<524288 / 256, 256>>>(out);
    }
    k_out<<<NBHW, 256>>>();
    k_assemble<<<OUT_ELEMS / 256, 256>>>(out);
}

// round 13
// speedup vs baseline: 1.6334x; 1.1050x over previous
#include <cuda_runtime.h>
#include <cstdint>

// Problem constants
#define B_  32
#define H_  4
#define L_  2048
#define D_  64
#define N_  32
#define P_  64
#define WN  63          // win_num
#define II  64          // N * win

#define WX_ELEMS 33030144   // B*H*II*WN*D
#define M_V      129024     // B*II*WN
#define NBHW     8064       // B*H*WN
#define OUT_ELEMS 16777216  // B*L*H*D

#define XS 68                              // X/T row stride (==4 mod 32: A-frag free)
#define MS 72                              // M row stride  (==8 mod 32: B-frag free)
#define SMEM_QK ((2*64*XS + 2*64*MS + 128) * 4)   // 72192 B

// Scratch (static device globals — allocation-free per harness rules)
__device__ float g_wx[WX_ELEMS];   // [b][h][i][w][d]
__device__ float g_v [WX_ELEMS];   // [b][i][w][h*64+d]
__device__ float g_adj[WX_ELEMS];  // [b][h][w][i][j]
__device__ float g_o [WX_ELEMS];   // [b][h][w][i][d]
__device__ uint32_t g_mh[4096], g_ml[4096];   // M = W1 W2^T, tf32 hi/lo
__device__ float g_uvs[130];                  // u[64], v[64], s=b1.b2

// ---------------------------------------------------------------------------
// tf32 helpers
// ---------------------------------------------------------------------------
__device__ __forceinline__ uint32_t f2tf32(float x) {
    uint32_t r;
    asm("cvt.rna.tf32.f32 %0, %1;" : "=r"(r) : "f"(x));
    return r;
}
__device__ __forceinline__ void split_tf32(float x, uint32_t& hi, uint32_t& lo) {
    asm("cvt.rna.tf32.f32 %0, %1;" : "=r"(hi) : "f"(x));
    float l = x - __uint_as_float(hi);
    asm("cvt.rna.tf32.f32 %0, %1;" : "=r"(lo) : "f"(l));
}
__device__ __forceinline__ void mma8(float* d, const uint32_t* a, const uint32_t* b) {
    asm volatile(
        "mma.sync.aligned.m16n8k8.row.col.f32.tf32.tf32.f32 "
        "{%0,%1,%2,%3}, {%4,%5,%6,%7}, {%8,%9}, {%0,%1,%2,%3};"
        : "+f"(d[0]), "+f"(d[1]), "+f"(d[2]), "+f"(d[3])
        : "r"(a[0]), "r"(a[1]), "r"(a[2]), "r"(a[3]), "r"(b[0]), "r"(b[1]));
}
// 3xTF32: d += a*b with near-fp32 accuracy (lo*hi + hi*lo + hi*hi)
__device__ __forceinline__ void mma3(float* d, const uint32_t* ah, const uint32_t* al,
                                     const uint32_t* bh, const uint32_t* bl) {
    mma8(d, al, bh);
    mma8(d, ah, bl);
    mma8(d, ah, bh);
}

// ---------------------------------------------------------------------------
// 0. k_prep (one block): M = W1 W2^T (fp32, then tf32 split), u = W1 b2,
//    v = W2 b1, s = b1.b2.   A = X M X^T + (Xu)⊗1 + 1⊗(Xv) + s.
// ---------------------------------------------------------------------------
__global__ __launch_bounds__(256) void k_prep(const float* __restrict__ W1,
                                              const float* __restrict__ b1,
                                              const float* __restrict__ W2,
                                              const float* __restrict__ b2) {
    __shared__ float W1s[64][65];
    __shared__ float W2s[64][65];
    int t = threadIdx.x;
#pragma unroll
    for (int it = 0; it < 16; ++it) {
        int i2 = t + it * 256;
        W1s[i2 >> 6][i2 & 63] = W1[i2];
        W2s[i2 >> 6][i2 & 63] = W2[i2];
    }
    __syncthreads();
    int d1 = t >> 2, part = t & 3;
#pragma unroll
    for (int m = 0; m < 16; ++m) {
        int d2 = part * 16 + m;
        float s = 0.f;
#pragma unroll 8
        for (int dd = 0; dd < 64; ++dd) s += W1s[d1][dd] * W2s[d2][dd];
        uint32_t hi, lo;
        split_tf32(s, hi, lo);
        g_mh[d1 * 64 + d2] = hi;
        g_ml[d1 * 64 + d2] = lo;
    }
    if (t < 64) {
        float su = 0.f, sv = 0.f;
#pragma unroll 8
        for (int dd = 0; dd < 64; ++dd) {
            su += W1s[t][dd] * b2[dd];
            sv += W2s[t][dd] * b1[dd];
        }
        g_uvs[t] = su;
        g_uvs[64 + t] = sv;
    }
    if (t == 0) {
        float s = 0.f;
        for (int dd = 0; dd < 64; ++dd) s += b1[dd] * b2[dd];
        g_uvs[128] = s;
    }
}

// ---------------------------------------------------------------------------
// 1. Gather wx, coalesced: one block per (bh, n); stage 64x64 x-tile in smem.
// ---------------------------------------------------------------------------
__global__ __launch_bounds__(256) void k_build_wx(const float* __restrict__ x) {
    __shared__ float xs[64][65];
    int bid = blockIdx.x;          // bh*32 + n, 4096 blocks
    int bh  = bid >> 5;
    int n   = bid & 31;
    int tid = threadIdx.x;
#pragma unroll
    for (int it = 0; it < 16; ++it) {
        int i2 = tid + it * 256;
        int rr = i2 >> 6, cc = i2 & 63;
        xs[rr][cc] = x[(bh * L_ + n * P_ + rr) * D_ + cc];
    }
    __syncthreads();
    float* dst = g_wx + bh * 258048 + n * 8064;
    for (int j = tid; j < 8064; j += 256) {
        int d  = j / 126;
        int r2 = j - d * 126;
        int row = (r2 >> 1) + (r2 & 1);     // w + e
        dst[j] = xs[row][d];
    }
}

// ---------------------------------------------------------------------------
// 2. Fused per (b,h,w): T = X M (3xTF32), A = T X^T (3xTF32) + Xu_i + Xv_j + s,
//    top-32 |.| keep (count-based), tanh, L1 row-normalize -> g_adj.
//    Buffers: Xh/Xl stride 68 (A-op & B-op), Mh/Ml stride 72 -> reused as
//    Th/Tl stride 68; A reuses Xh. Dyn smem 72192 B -> 3 blocks/SM.
// ---------------------------------------------------------------------------
__global__ __launch_bounds__(256) void k_qk_adj() {
    extern __shared__ uint32_t dyn_q[];
    uint32_t* Xh = dyn_q;                 // 64*XS
    uint32_t* Xl = Xh + 64 * XS;
    uint32_t* Mh = Xl + 64 * XS;          // 64*MS -> later Th (stride XS)
    uint32_t* Ml = Mh + 64 * MS;          // 64*MS -> later Tl
    float*    xu = (float*)(Ml + 64 * MS);   // 64 (includes +s)
    float*    xv = xu + 64;                  // 64

    int tid = threadIdx.x;
    int bid = blockIdx.x;
    int w   = bid % WN;
    int bh  = bid / WN;
#pragma unroll
    for (int it = 0; it < 16; ++it) {
        int i2 = tid + it * 256;
        int rr = i2 >> 6, cc = i2 & 63;
        uint32_t hi, lo;
        split_tf32(g_wx[((bh * II + rr) * WN + w) * D_ + cc], hi, lo);
        Xh[rr * XS + cc] = hi;  Xl[rr * XS + cc] = lo;
        Mh[rr * MS + cc] = g_mh[i2];
        Ml[rr * MS + cc] = g_ml[i2];
    }
    __syncthreads();

    // Xu[i] = X[i].u + s ; Xv[i] = X[i].v   (4 threads per row)
    {
        int r = tid >> 2, q = tid & 3;
        float su = 0.f, sv = 0.f;
#pragma unroll
        for (int k = 0; k < 16; ++k) {
            int d = q * 16 + k;
            float xval = __uint_as_float(Xh[r * XS + d]) +
                         __uint_as_float(Xl[r * XS + d]);
            su += xval * g_uvs[d];
            sv += xval * g_uvs[64 + d];
        }
        su += __shfl_xor_sync(0xffffffffu, su, 1);
        su += __shfl_xor_sync(0xffffffffu, su, 2);
        sv += __shfl_xor_sync(0xffffffffu, sv, 1);
        sv += __shfl_xor_sync(0xffffffffu, sv, 2);
        if (q == 0) { xu[r] = su + g_uvs[128]; xv[r] = sv; }
    }

    int warp = tid >> 5, lane = tid & 31;
    int g = lane >> 2, tq = lane & 3;
    int ms = (warp & 3) * 16;
    int nh = (warp >> 2) * 32;
    int r0 = (ms + g) * XS, r1 = (ms + g + 8) * XS;

    // ---- Phase A: T = X @ M. Warp tile 16 x 32.
    {
        float acc[4][4];
#pragma unroll
        for (int nt = 0; nt < 4; ++nt)
#pragma unroll
            for (int c = 0; c < 4; ++c) acc[nt][c] = 0.f;
#pragma unroll
        for (int ks = 0; ks < 8; ++ks) {
            int k0 = ks * 8;
            uint32_t ah[4], al[4];
            ah[0] = Xh[r0 + k0 + tq];     ah[1] = Xh[r1 + k0 + tq];
            ah[2] = Xh[r0 + k0 + tq + 4]; ah[3] = Xh[r1 + k0 + tq + 4];
            al[0] = Xl[r0 + k0 + tq];     al[1] = Xl[r1 + k0 + tq];
            al[2] = Xl[r0 + k0 + tq + 4]; al[3] = Xl[r1 + k0 + tq + 4];
            int b0 = (k0 + tq) * MS, b4 = (k0 + tq + 4) * MS;
#pragma unroll
            for (int nt = 0; nt < 4; ++nt) {
                int cb = nh + nt * 8 + g;
                uint32_t bhv[2], blv[2];
                bhv[0] = Mh[b0 + cb]; bhv[1] = Mh[b4 + cb];
                blv[0] = Ml[b0 + cb]; blv[1] = Ml[b4 + cb];
                mma3(acc[nt], ah, al, bhv, blv);
            }
        }
        __syncthreads();   // all M reads done before T overwrites the buffers
        uint32_t* Th = Mh;  // stride XS from here on
        uint32_t* Tl = Ml;
#pragma unroll
        for (int nt = 0; nt < 4; ++nt) {
            int n0 = nh + nt * 8 + 2 * tq;
            uint32_t hi, lo;
            split_tf32(acc[nt][0], hi, lo);
            Th[(ms + g) * XS + n0]     = hi; Tl[(ms + g) * XS + n0]     = lo;
            split_tf32(acc[nt][1], hi, lo);
            Th[(ms + g) * XS + n0 + 1] = hi; Tl[(ms + g) * XS + n0 + 1] = lo;
            split_tf32(acc[nt][2], hi, lo);
            Th[(ms + g + 8) * XS + n0]     = hi; Tl[(ms + g + 8) * XS + n0]     = lo;
            split_tf32(acc[nt][3], hi, lo);
            Th[(ms + g + 8) * XS + n0 + 1] = hi; Tl[(ms + g + 8) * XS + n0 + 1] = lo;
        }
        __syncthreads();
    }

    // ---- Phase B: A = T @ X^T. Warp tile 16 x 32.
    const uint32_t* Th = Mh;
    const uint32_t* Tl = Ml;
    float* Abuf = (float*)Xh;      // written after sync below
    {
        float acc[4][4];
#pragma unroll
        for (int nt = 0; nt < 4; ++nt)
#pragma unroll
            for (int c = 0; c < 4; ++c) acc[nt][c] = 0.f;
#pragma unroll
        for (int ks = 0; ks < 8; ++ks) {
            int k0 = ks * 8;
            uint32_t ah[4], al[4];
            ah[0] = Th[r0 + k0 + tq];     ah[1] = Th[r1 + k0 + tq];
            ah[2] = Th[r0 + k0 + tq + 4]; ah[3] = Th[r1 + k0 + tq + 4];
            al[0] = Tl[r0 + k0 + tq];     al[1] = Tl[r1 + k0 + tq];
            al[2] = Tl[r0 + k0 + tq + 4]; al[3] = Tl[r1 + k0 + tq + 4];
#pragma unroll
            for (int nt = 0; nt < 4; ++nt) {
                int j0 = (nh + nt * 8 + g) * XS;
                uint32_t bhv[2], blv[2];
                bhv[0] = Xh[j0 + k0 + tq]; bhv[1] = Xh[j0 + k0 + tq + 4];
                blv[0] = Xl[j0 + k0 + tq]; blv[1] = Xl[j0 + k0 + tq + 4];
                mma3(acc[nt], ah, al, bhv, blv);
            }
        }
        __syncthreads();   // all X reads done before A overwrites Xh
#pragma unroll
        for (int nt = 0; nt < 4; ++nt) {
            int n0 = nh + nt * 8 + 2 * tq;
            float v0 = xv[n0], v1 = xv[n0 + 1];
            Abuf[(ms + g) * XS + n0]         = acc[nt][0] + xu[ms + g] + v0;
            Abuf[(ms + g) * XS + n0 + 1]     = acc[nt][1] + xu[ms + g] + v1;
            Abuf[(ms + g + 8) * XS + n0]     = acc[nt][2] + xu[ms + g + 8] + v0;
            Abuf[(ms + g + 8) * XS + n0 + 1] = acc[nt][3] + xu[ms + g + 8] + v1;
        }
        __syncthreads();
    }

    // ---- ranking: shuffle-based top-32 count; tanh; L1 normalize ----
    int adjbase = bid * 4096;
    for (int r8 = 0; r8 < 8; ++r8) {
        int row = warp * 8 + r8;
        float a1 = Abuf[row * XS + lane];
        float a2 = Abuf[row * XS + lane + 32];
        float ab1 = fabsf(a1), ab2 = fabsf(a2);
        int c1 = 0, c2 = 0;
#pragma unroll
        for (int j = 0; j < 32; ++j) {
            float v = __shfl_sync(0xffffffffu, ab1, j);
            c1 += v < ab1;
            c2 += v < ab2;
        }
#pragma unroll
        for (int j = 0; j < 32; ++j) {
            float v = __shfl_sync(0xffffffffu, ab2, j);
            c1 += v < ab1;
            c2 += v < ab2;
        }
        float t1 = (c1 >= 32) ? tanhf(a1) : 0.f;
        float t2 = (c2 >= 32) ? tanhf(a2) : 0.f;
        float s = fabsf(t1) + fabsf(t2);
#pragma unroll
        for (int off = 16; off; off >>= 1) s += __shfl_xor_sync(0xffffffffu, s, off);
        float inv = 1.f / fmaxf(s, 1e-12f);
        g_adj[adjbase + row * 64 + lane]      = t1 * inv;
        g_adj[adjbase + row * 64 + lane + 32] = t2 * inv;
    }
}

// ---------------------------------------------------------------------------
// 3. v = v_in @ Wv + bv  (1xTF32). 64 rows x 256 cols per block.
// ---------------------------------------------------------------------------
__global__ __launch_bounds__(256) void k_v2(const float* __restrict__ Wv,
                                            const float* __restrict__ bv) {
    __shared__ uint32_t As[64 * 36];
    __shared__ __align__(16) uint32_t Bs[32 * 264];
    int tid  = threadIdx.x;
    int m0   = blockIdx.x * 64;
    int b    = blockIdx.x / 63;
    int rem0 = (blockIdx.x - b * 63) * 64;
    int warp = tid >> 5, lane = tid & 31;
    int g = lane >> 2, tq = lane & 3;
    int ms = (warp & 3) * 16;
    int nh = (warp >> 2) * 128;
    float acc[16][4];
#pragma unroll
    for (int nt = 0; nt < 16; ++nt)
#pragma unroll
        for (int c = 0; c < 4; ++c) acc[nt][c] = 0.f;

    for (int ch = 0; ch < 8; ++ch) {       // global k = ch*32 + kk; h = ch>>1
#pragma unroll
        for (int it = 0; it < 8; ++it) {   // A: 64x32, cvt tf32 at store
            int i2 = tid + it * 256;
            int rr = i2 >> 5, kkc = i2 & 31;
            int rem = rem0 + rr;
            int i  = rem / WN;
            int ww = rem - i * WN;
            As[rr * 36 + kkc] = f2tf32(
                g_wx[(((b * H_ + (ch >> 1)) * II + i) * WN + ww) * D_ +
                     (ch & 1) * 32 + kkc]);
        }
#pragma unroll
        for (int it = 0; it < 8; ++it) {   // B: 32x256, cvt tf32 at store
            int i4 = tid + it * 256;
            int r  = i4 >> 6;
            int c  = (i4 & 63) * 4;
            float4 v4 = *(const float4*)&Wv[(ch * 32 + r) * 256 + c];
            uint4 t;
            t.x = f2tf32(v4.x); t.y = f2tf32(v4.y);
            t.z = f2tf32(v4.z); t.w = f2tf32(v4.w);
            *(uint4*)&Bs[r * 264 + c] = t;
        }
        __syncthreads();
#pragma unroll
        for (int ks = 0; ks < 4; ++ks) {
            int k0 = ks * 8;
            uint32_t a[4];
            a[0] = As[(ms + g) * 36 + k0 + tq];
            a[1] = As[(ms + g + 8) * 36 + k0 + tq];
            a[2] = As[(ms + g) * 36 + k0 + tq + 4];
            a[3] = As[(ms + g + 8) * 36 + k0 + tq + 4];
#pragma unroll
            for (int nt = 0; nt < 16; ++nt) {
                int n0 = nh + nt * 8 + g;
                uint32_t bb[2];
                bb[0] = Bs[(k0 + tq) * 264 + n0];
                bb[1] = Bs[(k0 + tq + 4) * 264 + n0];
                mma8(acc[nt], a, bb);
            }
        }
        __syncthreads();
    }
#pragma unroll
    for (int nt = 0; nt < 16; ++nt) {
        int n0 = nh + nt * 8 + 2 * tq;
        float bb0 = bv[n0], bb1 = bv[n0 + 1];
        g_v[(m0 + ms + g) * 256 + n0]         = acc[nt][0] + bb0;
        g_v[(m0 + ms + g) * 256 + n0 + 1]     = acc[nt][1] + bb1;
        g_v[(m0 + ms + g + 8) * 256 + n0]     = acc[nt][2] + bb0;
        g_v[(m0 + ms + g + 8) * 256 + n0 + 1] = acc[nt][3] + bb1;
    }
}

// ---------------------------------------------------------------------------
// 4. loss = mean_{b,h,i,j} var_w(adj)   (ddof=0, two-pass)
// ---------------------------------------------------------------------------
__global__ void k_loss_zero(float* __restrict__ out) { out[OUT_ELEMS] = 0.f; }

__global__ __launch_bounds__(256) void k_loss(float* __restrict__ out) {
    int idx = blockIdx.x * 256 + threadIdx.x;  // over B*H*64*64 = 524288
    int bh  = idx >> 12;
    int ij  = idx & 4095;
    const float* p = g_adj + bh * (WN * 4096) + ij;
    float s1 = 0.f;
#pragma unroll 7
    for (int w = 0; w < WN; ++w) s1 += p[w * 4096];
    float m = s1 * (1.f / 63.f);
    float s2 = 0.f;
#pragma unroll 7
    for (int w = 0; w < WN; ++w) { float dv = p[w * 4096] - m; s2 += dv * dv; }
    float var = s2 * (1.f / 63.f);
    __shared__ float red[256];
    red[threadIdx.x] = var;
    __syncthreads();
    for (int off = 128; off; off >>= 1) {
        if (threadIdx.x < off) red[threadIdx.x] += red[threadIdx.x + off];
        __syncthreads();
    }
    if (threadIdx.x == 0) atomicAdd(out + OUT_ELEMS, red[0] * (1.f / 524288.f));
}

// ---------------------------------------------------------------------------
// 5. Per (b,h,w): O = A_w @ V_w (1xTF32, pre-converted, conflict-free).
// ---------------------------------------------------------------------------
__global__ __launch_bounds__(256) void k_out() {
    __shared__ uint32_t As[64 * 68];
    __shared__ uint32_t Vs[64 * 72];
    int tid = threadIdx.x;
    int bid = blockIdx.x;
    int w   = bid % WN;
    int bh  = bid / WN;
    int b   = bh >> 2;
    int h   = bh & 3;
#pragma unroll
    for (int it = 0; it < 16; ++it) {
        int i2 = tid + it * 256;
        int rr = i2 >> 6, cc = i2 & 63;
        As[rr * 68 + cc] = f2tf32(g_adj[bid * 4096 + i2]);
        Vs[rr * 72 + cc] = f2tf32(g_v[((b * II + rr) * WN + w) * 256 + h * 64 + cc]);
    }
    __syncthreads();
    int warp = tid >> 5, lane = tid & 31;
    int g = lane >> 2, tq = lane & 3;
    int ms = (warp & 3) * 16;
    int nh = (warp >> 2) * 32;
    float acc[4][4];
#pragma unroll
    for (int nt = 0; nt < 4; ++nt)
#pragma unroll
        for (int c = 0; c < 4; ++c) acc[nt][c] = 0.f;
#pragma unroll
    for (int ks = 0; ks < 8; ++ks) {
        int k0 = ks * 8;
        uint32_t a[4];
        a[0] = As[(ms + g) * 68 + k0 + tq];
        a[1] = As[(ms + g + 8) * 68 + k0 + tq];
        a[2] = As[(ms + g) * 68 + k0 + tq + 4];
        a[3] = As[(ms + g + 8) * 68 + k0 + tq + 4];
#pragma unroll
        for (int nt = 0; nt < 4; ++nt) {
            int n0 = nh + nt * 8 + g;
            uint32_t bb[2];
            bb[0] = Vs[(k0 + tq) * 72 + n0];
            bb[1] = Vs[(k0 + tq + 4) * 72 + n0];
            mma8(acc[nt], a, bb);
        }
    }
#pragma unroll
    for (int nt = 0; nt < 4; ++nt) {
        int n0 = nh + nt * 8 + 2 * tq;
        g_o[bid * 4096 + (ms + g) * 64 + n0]         = acc[nt][0];
        g_o[bid * 4096 + (ms + g) * 64 + n0 + 1]     = acc[nt][1];
        g_o[bid * 4096 + (ms + g + 8) * 64 + n0]     = acc[nt][2];
        g_o[bid * 4096 + (ms + g + 8) * 64 + n0 + 1] = acc[nt][3];
    }
}

// ---------------------------------------------------------------------------
// 6. Final assembly: closed form of pad + pair-mean epilogue.
// ---------------------------------------------------------------------------
__global__ __launch_bounds__(256) void k_assemble(float* __restrict__ out) {
    int idx = blockIdx.x * 256 + threadIdx.x;  // exact OUT_ELEMS
    int d = idx & 63;
    int h = (idx >> 6) & 3;
    int p = (idx >> 8) & 63;
    int n = (idx >> 14) & 31;
    int b = idx >> 19;
    int bh = b * 4 + h;
    float val;
    if (p == 0) {
        val = g_o[((bh * WN + 0) * 64 + 2 * n) * 64 + d];
    } else if (p == 63) {
        val = g_o[((bh * WN + 62) * 64 + 2 * n + 1) * 64 + d];
    } else {
        float o0 = g_o[((bh * WN + p) * 64 + 2 * n) * 64 + d];
        float o1 = g_o[((bh * WN + p - 1) * 64 + 2 * n + 1) * 64 + d];
        val = 0.5f * (o0 + o1);
    }
    out[idx] = val;
}

// ---------------------------------------------------------------------------
// Launch order: k_qk_adj kept in slot 4 (ncu profiles the 4th launch).
// Deps: prep before qk_adj; build_wx before v2/qk_adj; qk_adj before
// loss/out; v2 before out; out before assemble.
// ---------------------------------------------------------------------------
extern "C" void kernel_launch(void* const* d_in, const int* in_sizes, int n_in,
                              void* d_out, int out_size) {
    const float* x  = (const float*)d_in[0];
    const float* W1 = (const float*)d_in[1];
    const float* b1 = (const float*)d_in[2];
    const float* W2 = (const float*)d_in[3];
    const float* b2 = (const float*)d_in[4];
    const float* Wv = (const float*)d_in[5];
    const float* bv = (const float*)d_in[6];
    float* out = (float*)d_out;

    cudaFuncSetAttribute(k_qk_adj, cudaFuncAttributeMaxDynamicSharedMemorySize,
                         SMEM_QK);

    k_build_wx<<<4096, 256>>>(x);
    k_v2<<<M_V / 64, 256>>>(Wv, bv);
    k_prep<<<1, 256>>>(W1, b1, W2, b2);
    k_qk_adj<<<NBHW, 256, SMEM_QK>>>();
    if (out_size > OUT_ELEMS) {
        k_loss_zero<<<1, 1>>>(out);
        k_loss<<<524288 / 256, 256>>>(out);
    }
    k_out<<<NBHW, 256>>>();
    k_assemble<<<OUT_ELEMS / 256, 256>>>(out);
}

// round 15
// speedup vs baseline: 1.8674x; 1.1432x over previous
#include <cuda_runtime.h>
#include <cstdint>

// Problem constants
#define B_  32
#define H_  4
#define L_  2048
#define D_  64
#define N_  32
#define P_  64
#define WN  63          // win_num
#define II  64          // N * win

#define WX_ELEMS 33030144   // B*H*II*WN*D
#define M_V      129024     // B*II*WN
#define NBHW     8064       // B*H*WN
#define OUT_ELEMS 16777216  // B*L*H*D

#define XS 68                              // X/T row stride (==4 mod 32: A-frag free)
#define MS 72                              // M row stride  (==8 mod 32: B-frag free)
#define SMEM_QK ((2*64*XS + 2*64*MS + 128) * 4)   // 72192 B

// Scratch (static device globals — allocation-free per harness rules)
__device__ float g_wx[WX_ELEMS];   // [b][h][i][w][d]
__device__ float g_v [WX_ELEMS];   // [b][i][w][h*64+d]
__device__ float g_adj[WX_ELEMS];  // [b][h][w][i][j]
__device__ uint32_t g_mh[4096], g_ml[4096];   // M = W1 W2^T, tf32 hi/lo
__device__ float g_uvs[130];                  // u[64], v[64], s=b1.b2

// ---------------------------------------------------------------------------
// tf32 helpers
// ---------------------------------------------------------------------------
__device__ __forceinline__ uint32_t f2tf32(float x) {
    uint32_t r;
    asm("cvt.rna.tf32.f32 %0, %1;" : "=r"(r) : "f"(x));
    return r;
}
__device__ __forceinline__ void split_tf32(float x, uint32_t& hi, uint32_t& lo) {
    asm("cvt.rna.tf32.f32 %0, %1;" : "=r"(hi) : "f"(x));
    float l = x - __uint_as_float(hi);
    asm("cvt.rna.tf32.f32 %0, %1;" : "=r"(lo) : "f"(l));
}
__device__ __forceinline__ void mma8(float* d, const uint32_t* a, const uint32_t* b) {
    asm volatile(
        "mma.sync.aligned.m16n8k8.row.col.f32.tf32.tf32.f32 "
        "{%0,%1,%2,%3}, {%4,%5,%6,%7}, {%8,%9}, {%0,%1,%2,%3};"
        : "+f"(d[0]), "+f"(d[1]), "+f"(d[2]), "+f"(d[3])
        : "r"(a[0]), "r"(a[1]), "r"(a[2]), "r"(a[3]), "r"(b[0]), "r"(b[1]));
}
// 3xTF32: d += a*b with near-fp32 accuracy (lo*hi + hi*lo + hi*hi)
__device__ __forceinline__ void mma3(float* d, const uint32_t* ah, const uint32_t* al,
                                     const uint32_t* bh, const uint32_t* bl) {
    mma8(d, al, bh);
    mma8(d, ah, bl);
    mma8(d, ah, bh);
}

// ---------------------------------------------------------------------------
// 0. k_prep (one block): M = W1 W2^T (fp32, then tf32 split), u = W1 b2,
//    v = W2 b1, s = b1.b2.   A = X M X^T + (Xu)⊗1 + 1⊗(Xv) + s.
// ---------------------------------------------------------------------------
__global__ __launch_bounds__(256) void k_prep(const float* __restrict__ W1,
                                              const float* __restrict__ b1,
                                              const float* __restrict__ W2,
                                              const float* __restrict__ b2) {
    __shared__ float W1s[64][65];
    __shared__ float W2s[64][65];
    int t = threadIdx.x;
#pragma unroll
    for (int it = 0; it < 16; ++it) {
        int i2 = t + it * 256;
        W1s[i2 >> 6][i2 & 63] = W1[i2];
        W2s[i2 >> 6][i2 & 63] = W2[i2];
    }
    __syncthreads();
    int d1 = t >> 2, part = t & 3;
#pragma unroll
    for (int m = 0; m < 16; ++m) {
        int d2 = part * 16 + m;
        float s = 0.f;
#pragma unroll 8
        for (int dd = 0; dd < 64; ++dd) s += W1s[d1][dd] * W2s[d2][dd];
        uint32_t hi, lo;
        split_tf32(s, hi, lo);
        g_mh[d1 * 64 + d2] = hi;
        g_ml[d1 * 64 + d2] = lo;
    }
    if (t < 64) {
        float su = 0.f, sv = 0.f;
#pragma unroll 8
        for (int dd = 0; dd < 64; ++dd) {
            su += W1s[t][dd] * b2[dd];
            sv += W2s[t][dd] * b1[dd];
        }
        g_uvs[t] = su;
        g_uvs[64 + t] = sv;
    }
    if (t == 0) {
        float s = 0.f;
        for (int dd = 0; dd < 64; ++dd) s += b1[dd] * b2[dd];
        g_uvs[128] = s;
    }
}

// ---------------------------------------------------------------------------
// 1. Gather wx, coalesced: one block per (bh, n); stage 64x64 x-tile in smem.
// ---------------------------------------------------------------------------
__global__ __launch_bounds__(256) void k_build_wx(const float* __restrict__ x) {
    __shared__ float xs[64][65];
    int bid = blockIdx.x;          // bh*32 + n, 4096 blocks
    int bh  = bid >> 5;
    int n   = bid & 31;
    int tid = threadIdx.x;
#pragma unroll
    for (int it = 0; it < 16; ++it) {
        int i2 = tid + it * 256;
        int rr = i2 >> 6, cc = i2 & 63;
        xs[rr][cc] = x[(bh * L_ + n * P_ + rr) * D_ + cc];
    }
    __syncthreads();
    float* dst = g_wx + bh * 258048 + n * 8064;
    for (int j = tid; j < 8064; j += 256) {
        int d  = j / 126;
        int r2 = j - d * 126;
        int row = (r2 >> 1) + (r2 & 1);     // w + e
        dst[j] = xs[row][d];
    }
}

// ---------------------------------------------------------------------------
// 2. Fused per (b,h,w): T = X M (3xTF32), A = T X^T (3xTF32) + Xu_i + Xv_j + s,
//    top-32 |.| keep via ballot-quickselect threshold (exactly equivalent to
//    the count rule incl. duplicates), tanh, L1 row-normalize -> g_adj.
// ---------------------------------------------------------------------------
__global__ __launch_bounds__(256) void k_qk_adj() {
    extern __shared__ uint32_t dyn_q[];
    uint32_t* Xh = dyn_q;                 // 64*XS
    uint32_t* Xl = Xh + 64 * XS;
    uint32_t* Mh = Xl + 64 * XS;          // 64*MS -> later Th (stride XS)
    uint32_t* Ml = Mh + 64 * MS;          // 64*MS -> later Tl
    float*    xu = (float*)(Ml + 64 * MS);   // 64 (includes +s)
    float*    xv = xu + 64;                  // 64

    int tid = threadIdx.x;
    int bid = blockIdx.x;
    int w   = bid % WN;
    int bh  = bid / WN;
#pragma unroll
    for (int it = 0; it < 16; ++it) {
        int i2 = tid + it * 256;
        int rr = i2 >> 6, cc = i2 & 63;
        uint32_t hi, lo;
        split_tf32(g_wx[((bh * II + rr) * WN + w) * D_ + cc], hi, lo);
        Xh[rr * XS + cc] = hi;  Xl[rr * XS + cc] = lo;
        Mh[rr * MS + cc] = g_mh[i2];
        Ml[rr * MS + cc] = g_ml[i2];
    }
    __syncthreads();

    // Xu[i] = X[i].u + s ; Xv[i] = X[i].v   (4 threads per row)
    {
        int r = tid >> 2, q = tid & 3;
        float su = 0.f, sv = 0.f;
#pragma unroll
        for (int k = 0; k < 16; ++k) {
            int d = q * 16 + k;
            float xval = __uint_as_float(Xh[r * XS + d]) +
                         __uint_as_float(Xl[r * XS + d]);
            su += xval * g_uvs[d];
            sv += xval * g_uvs[64 + d];
        }
        su += __shfl_xor_sync(0xffffffffu, su, 1);
        su += __shfl_xor_sync(0xffffffffu, su, 2);
        sv += __shfl_xor_sync(0xffffffffu, sv, 1);
        sv += __shfl_xor_sync(0xffffffffu, sv, 2);
        if (q == 0) { xu[r] = su + g_uvs[128]; xv[r] = sv; }
    }

    int warp = tid >> 5, lane = tid & 31;
    int g = lane >> 2, tq = lane & 3;
    int ms = (warp & 3) * 16;
    int nh = (warp >> 2) * 32;
    int r0 = (ms + g) * XS, r1 = (ms + g + 8) * XS;

    // ---- Phase A: T = X @ M. Warp tile 16 x 32.
    {
        float acc[4][4];
#pragma unroll
        for (int nt = 0; nt < 4; ++nt)
#pragma unroll
            for (int c = 0; c < 4; ++c) acc[nt][c] = 0.f;
#pragma unroll
        for (int ks = 0; ks < 8; ++ks) {
            int k0 = ks * 8;
            uint32_t ah[4], al[4];
            ah[0] = Xh[r0 + k0 + tq];     ah[1] = Xh[r1 + k0 + tq];
            ah[2] = Xh[r0 + k0 + tq + 4]; ah[3] = Xh[r1 + k0 + tq + 4];
            al[0] = Xl[r0 + k0 + tq];     al[1] = Xl[r1 + k0 + tq];
            al[2] = Xl[r0 + k0 + tq + 4]; al[3] = Xl[r1 + k0 + tq + 4];
            int b0 = (k0 + tq) * MS, b4 = (k0 + tq + 4) * MS;
#pragma unroll
            for (int nt = 0; nt < 4; ++nt) {
                int cb = nh + nt * 8 + g;
                uint32_t bhv[2], blv[2];
                bhv[0] = Mh[b0 + cb]; bhv[1] = Mh[b4 + cb];
                blv[0] = Ml[b0 + cb]; blv[1] = Ml[b4 + cb];
                mma3(acc[nt], ah, al, bhv, blv);
            }
        }
        __syncthreads();   // all M reads done before T overwrites the buffers
        uint32_t* Th = Mh;  // stride XS from here on
        uint32_t* Tl = Ml;
#pragma unroll
        for (int nt = 0; nt < 4; ++nt) {
            int n0 = nh + nt * 8 + 2 * tq;
            uint32_t hi, lo;
            split_tf32(acc[nt][0], hi, lo);
            Th[(ms + g) * XS + n0]     = hi; Tl[(ms + g) * XS + n0]     = lo;
            split_tf32(acc[nt][1], hi, lo);
            Th[(ms + g) * XS + n0 + 1] = hi; Tl[(ms + g) * XS + n0 + 1] = lo;
            split_tf32(acc[nt][2], hi, lo);
            Th[(ms + g + 8) * XS + n0]     = hi; Tl[(ms + g + 8) * XS + n0]     = lo;
            split_tf32(acc[nt][3], hi, lo);
            Th[(ms + g + 8) * XS + n0 + 1] = hi; Tl[(ms + g + 8) * XS + n0 + 1] = lo;
        }
        __syncthreads();
    }

    // ---- Phase B: A = T @ X^T. Warp tile 16 x 32.
    const uint32_t* Th = Mh;
    const uint32_t* Tl = Ml;
    float* Abuf = (float*)Xh;      // written after sync below
    {
        float acc[4][4];
#pragma unroll
        for (int nt = 0; nt < 4; ++nt)
#pragma unroll
            for (int c = 0; c < 4; ++c) acc[nt][c] = 0.f;
#pragma unroll
        for (int ks = 0; ks < 8; ++ks) {
            int k0 = ks * 8;
            uint32_t ah[4], al[4];
            ah[0] = Th[r0 + k0 + tq];     ah[1] = Th[r1 + k0 + tq];
            ah[2] = Th[r0 + k0 + tq + 4]; ah[3] = Th[r1 + k0 + tq + 4];
            al[0] = Tl[r0 + k0 + tq];     al[1] = Tl[r1 + k0 + tq];
            al[2] = Tl[r0 + k0 + tq + 4]; al[3] = Tl[r1 + k0 + tq + 4];
#pragma unroll
            for (int nt = 0; nt < 4; ++nt) {
                int j0 = (nh + nt * 8 + g) * XS;
                uint32_t bhv[2], blv[2];
                bhv[0] = Xh[j0 + k0 + tq]; bhv[1] = Xh[j0 + k0 + tq + 4];
                blv[0] = Xl[j0 + k0 + tq]; blv[1] = Xl[j0 + k0 + tq + 4];
                mma3(acc[nt], ah, al, bhv, blv);
            }
        }
        __syncthreads();   // all X reads done before A overwrites Xh
#pragma unroll
        for (int nt = 0; nt < 4; ++nt) {
            int n0 = nh + nt * 8 + 2 * tq;
            float v0 = xv[n0], v1 = xv[n0 + 1];
            Abuf[(ms + g) * XS + n0]         = acc[nt][0] + xu[ms + g] + v0;
            Abuf[(ms + g) * XS + n0 + 1]     = acc[nt][1] + xu[ms + g] + v1;
            Abuf[(ms + g + 8) * XS + n0]     = acc[nt][2] + xu[ms + g + 8] + v0;
            Abuf[(ms + g + 8) * XS + n0 + 1] = acc[nt][3] + xu[ms + g + 8] + v1;
        }
        __syncthreads();
    }

    // ---- ranking: ballot-quickselect threshold t = 32nd-smallest |a|;
    //      keep iff |a| > t  (== count rule); tanh; L1 normalize ----
    const unsigned FULL = 0xffffffffu;
    int adjbase = bid * 4096;
    for (int r8 = 0; r8 < 8; ++r8) {
        int row = warp * 8 + r8;
        float a1 = Abuf[row * XS + lane];
        float a2 = Abuf[row * XS + lane + 32];
        float k0 = fabsf(a1), k1 = fabsf(a2);
        float lo = -1.f, hi = __int_as_float(0x7f800000);
        float t = hi;
        for (int it = 0; it < 64; ++it) {
            unsigned m0 = __ballot_sync(FULL, k0 > lo && k0 < hi);
            float piv;
            if (m0) {
                piv = __shfl_sync(FULL, k0, __ffs(m0) - 1);
            } else {
                unsigned m1 = __ballot_sync(FULL, k1 > lo && k1 < hi);
                if (!m1) break;                 // safety; unreachable
                piv = __shfl_sync(FULL, k1, __ffs(m1) - 1);
            }
            int c = __popc(__ballot_sync(FULL, k0 < piv)) +
                    __popc(__ballot_sync(FULL, k1 < piv));
            if (c > 31) {
                hi = piv;
            } else {
                int cle = __popc(__ballot_sync(FULL, k0 <= piv)) +
                          __popc(__ballot_sync(FULL, k1 <= piv));
                if (cle >= 32) { t = piv; break; }
                lo = piv;
            }
        }
        float t1 = (k0 > t) ? tanhf(a1) : 0.f;
        float t2 = (k1 > t) ? tanhf(a2) : 0.f;
        float s = fabsf(t1) + fabsf(t2);
#pragma unroll
        for (int off = 16; off; off >>= 1) s += __shfl_xor_sync(FULL, s, off);
        float inv = 1.f / fmaxf(s, 1e-12f);
        g_adj[adjbase + row * 64 + lane]      = t1 * inv;
        g_adj[adjbase + row * 64 + lane + 32] = t2 * inv;
    }
}

// ---------------------------------------------------------------------------
// 3. v = v_in @ Wv + bv  (1xTF32). 64 rows x 256 cols per block.
// ---------------------------------------------------------------------------
__global__ __launch_bounds__(256) void k_v2(const float* __restrict__ Wv,
                                            const float* __restrict__ bv) {
    __shared__ uint32_t As[64 * 36];
    __shared__ __align__(16) uint32_t Bs[32 * 264];
    int tid  = threadIdx.x;
    int m0   = blockIdx.x * 64;
    int b    = blockIdx.x / 63;
    int rem0 = (blockIdx.x - b * 63) * 64;
    int warp = tid >> 5, lane = tid & 31;
    int g = lane >> 2, tq = lane & 3;
    int ms = (warp & 3) * 16;
    int nh = (warp >> 2) * 128;
    float acc[16][4];
#pragma unroll
    for (int nt = 0; nt < 16; ++nt)
#pragma unroll
        for (int c = 0; c < 4; ++c) acc[nt][c] = 0.f;

    for (int ch = 0; ch < 8; ++ch) {       // global k = ch*32 + kk; h = ch>>1
#pragma unroll
        for (int it = 0; it < 8; ++it) {   // A: 64x32, cvt tf32 at store
            int i2 = tid + it * 256;
            int rr = i2 >> 5, kkc = i2 & 31;
            int rem = rem0 + rr;
            int i  = rem / WN;
            int ww = rem - i * WN;
            As[rr * 36 + kkc] = f2tf32(
                g_wx[(((b * H_ + (ch >> 1)) * II + i) * WN + ww) * D_ +
                     (ch & 1) * 32 + kkc]);
        }
#pragma unroll
        for (int it = 0; it < 8; ++it) {   // B: 32x256, cvt tf32 at store
            int i4 = tid + it * 256;
            int r  = i4 >> 6;
            int c  = (i4 & 63) * 4;
            float4 v4 = *(const float4*)&Wv[(ch * 32 + r) * 256 + c];
            uint4 t;
            t.x = f2tf32(v4.x); t.y = f2tf32(v4.y);
            t.z = f2tf32(v4.z); t.w = f2tf32(v4.w);
            *(uint4*)&Bs[r * 264 + c] = t;
        }
        __syncthreads();
#pragma unroll
        for (int ks = 0; ks < 4; ++ks) {
            int k0 = ks * 8;
            uint32_t a[4];
            a[0] = As[(ms + g) * 36 + k0 + tq];
            a[1] = As[(ms + g + 8) * 36 + k0 + tq];
            a[2] = As[(ms + g) * 36 + k0 + tq + 4];
            a[3] = As[(ms + g + 8) * 36 + k0 + tq + 4];
#pragma unroll
            for (int nt = 0; nt < 16; ++nt) {
                int n0 = nh + nt * 8 + g;
                uint32_t bb[2];
                bb[0] = Bs[(k0 + tq) * 264 + n0];
                bb[1] = Bs[(k0 + tq + 4) * 264 + n0];
                mma8(acc[nt], a, bb);
            }
        }
        __syncthreads();
    }
#pragma unroll
    for (int nt = 0; nt < 16; ++nt) {
        int n0 = nh + nt * 8 + 2 * tq;
        float bb0 = bv[n0], bb1 = bv[n0 + 1];
        g_v[(m0 + ms + g) * 256 + n0]         = acc[nt][0] + bb0;
        g_v[(m0 + ms + g) * 256 + n0 + 1]     = acc[nt][1] + bb1;
        g_v[(m0 + ms + g + 8) * 256 + n0]     = acc[nt][2] + bb0;
        g_v[(m0 + ms + g + 8) * 256 + n0 + 1] = acc[nt][3] + bb1;
    }
}

// ---------------------------------------------------------------------------
// 4. loss = mean_{b,h,i,j} var_w(adj)   (ddof=0, two-pass)
// ---------------------------------------------------------------------------
__global__ void k_loss_zero(float* __restrict__ out) { out[OUT_ELEMS] = 0.f; }

__global__ __launch_bounds__(256) void k_loss(float* __restrict__ out) {
    int idx = blockIdx.x * 256 + threadIdx.x;  // over B*H*64*64 = 524288
    int bh  = idx >> 12;
    int ij  = idx & 4095;
    const float* p = g_adj + bh * (WN * 4096) + ij;
    float s1 = 0.f;
#pragma unroll 7
    for (int w = 0; w < WN; ++w) s1 += p[w * 4096];
    float m = s1 * (1.f / 63.f);
    float s2 = 0.f;
#pragma unroll 7
    for (int w = 0; w < WN; ++w) { float dv = p[w * 4096] - m; s2 += dv * dv; }
    float var = s2 * (1.f / 63.f);
    __shared__ float red[256];
    red[threadIdx.x] = var;
    __syncthreads();
    for (int off = 128; off; off >>= 1) {
        if (threadIdx.x < off) red[threadIdx.x] += red[threadIdx.x + off];
        __syncthreads();
    }
    if (threadIdx.x == 0) atomicAdd(out + OUT_ELEMS, red[0] * (1.f / 524288.f));
}

// ---------------------------------------------------------------------------
// 5. Fused O-GEMM + epilogue. One block per (bh, 8-p group): computes the
//    needed O[w] tiles (incl. one boundary recompute), keeps previous tile's
//    odd rows in smem, emits out directly.
//    out[b, n*64+p, h*64+d]: p==0 -> O[0][2n]; p==63 -> O[62][2n+1];
//    else 0.5*(O[p][2n] + O[p-1][2n+1]).
// ---------------------------------------------------------------------------
__global__ __launch_bounds__(256) void k_out2(float* __restrict__ out_) {
    __shared__ uint32_t As[64 * 68];
    __shared__ uint32_t Vs[64 * 72];
    __shared__ float Oodd[32 * 68];

    int tid = threadIdx.x;
    int bh  = blockIdx.x >> 3;
    int gix = blockIdx.x & 7;
    int b = bh >> 2, h = bh & 3;
    int w0  = gix * 8;
    int wlo = (gix == 0) ? 0 : w0 - 1;
    int whi = (w0 + 7 > 62) ? 62 : w0 + 7;
    int warp = tid >> 5, lane = tid & 31;
    int g = lane >> 2, tq = lane & 3;
    int ms = (warp & 3) * 16;
    int nh = (warp >> 2) * 32;

    for (int w = wlo; w <= whi; ++w) {
        int bidw = bh * WN + w;
#pragma unroll
        for (int it = 0; it < 16; ++it) {
            int i2 = tid + it * 256;
            int rr = i2 >> 6, cc = i2 & 63;
            As[rr * 68 + cc] = f2tf32(g_adj[bidw * 4096 + i2]);
            Vs[rr * 72 + cc] = f2tf32(g_v[((b * II + rr) * WN + w) * 256 + h * 64 + cc]);
        }
        __syncthreads();

        float acc[4][4];
#pragma unroll
        for (int nt = 0; nt < 4; ++nt)
#pragma unroll
            for (int c = 0; c < 4; ++c) acc[nt][c] = 0.f;
#pragma unroll
        for (int ks = 0; ks < 8; ++ks) {
            int k0 = ks * 8;
            uint32_t a[4];
            a[0] = As[(ms + g) * 68 + k0 + tq];
            a[1] = As[(ms + g + 8) * 68 + k0 + tq];
            a[2] = As[(ms + g) * 68 + k0 + tq + 4];
            a[3] = As[(ms + g + 8) * 68 + k0 + tq + 4];
#pragma unroll
            for (int nt = 0; nt < 4; ++nt) {
                int n0 = nh + nt * 8 + g;
                uint32_t bb[2];
                bb[0] = Vs[(k0 + tq) * 72 + n0];
                bb[1] = Vs[(k0 + tq + 4) * 72 + n0];
                mma8(acc[nt], a, bb);
            }
        }

        // emit out[p=w] from even rows (+ previous tile's odd rows)
        if (w >= w0) {
            int p = w;
#pragma unroll
            for (int half = 0; half < 2; ++half) {
                int r = ms + g + half * 8;
                if ((r & 1) == 0) {
                    int n = r >> 1;
                    float* op = out_ + ((size_t)(b * 2048 + n * 64 + p)) * 256 + h * 64;
#pragma unroll
                    for (int nt = 0; nt < 4; ++nt) {
                        int c0 = nh + nt * 8 + 2 * tq;
                        float v0 = acc[nt][half * 2 + 0];
                        float v1 = acc[nt][half * 2 + 1];
                        if (p == 0) {
                            op[c0] = v0;  op[c0 + 1] = v1;
                        } else {
                            op[c0]     = 0.5f * (v0 + Oodd[n * 68 + c0]);
                            op[c0 + 1] = 0.5f * (v1 + Oodd[n * 68 + c0 + 1]);
                        }
                    }
                }
            }
        }
        __syncthreads();   // Oodd reads done before overwrite

        // store this tile's odd rows for the next p
#pragma unroll
        for (int half = 0; half < 2; ++half) {
            int r = ms + g + half * 8;
            if (r & 1) {
                int n = r >> 1;
#pragma unroll
                for (int nt = 0; nt < 4; ++nt) {
                    int c0 = nh + nt * 8 + 2 * tq;
                    Oodd[n * 68 + c0]     = acc[nt][half * 2 + 0];
                    Oodd[n * 68 + c0 + 1] = acc[nt][half * 2 + 1];
                }
            }
        }
        __syncthreads();
    }

    // p = 63: last group's final odd rows
    if (gix == 7) {
        for (int i2 = tid; i2 < 2048; i2 += 256) {
            int n = i2 >> 6, d = i2 & 63;
            out_[((size_t)(b * 2048 + n * 64 + 63)) * 256 + h * 64 + d] =
                Oodd[n * 68 + d];
        }
    }
}

// ---------------------------------------------------------------------------
// Launch order: k_qk_adj kept in slot 4 (ncu profiles the 4th launch).
// Deps: prep before qk_adj; build_wx before v2/qk_adj; qk_adj before
// loss/out2; v2 before out2.
// ---------------------------------------------------------------------------
extern "C" void kernel_launch(void* const* d_in, const int* in_sizes, int n_in,
                              void* d_out, int out_size) {
    const float* x  = (const float*)d_in[0];
    const float* W1 = (const float*)d_in[1];
    const float* b1 = (const float*)d_in[2];
    const float* W2 = (const float*)d_in[3];
    const float* b2 = (const float*)d_in[4];
    const float* Wv = (const float*)d_in[5];
    const float* bv = (const float*)d_in[6];
    float* out = (float*)d_out;

    cudaFuncSetAttribute(k_qk_adj, cudaFuncAttributeMaxDynamicSharedMemorySize,
                         SMEM_QK);

    k_build_wx<<<4096, 256>>>(x);
    k_v2<<<M_V / 64, 256>>>(Wv, bv);
    k_prep<<<1, 256>>>(W1, b1, W2, b2);
    k_qk_adj<<<NBHW, 256, SMEM_QK>>>();
    if (out_size > OUT_ELEMS) {
        k_loss_zero<<<1, 1>>>(out);
        k_loss<<<524288 / 256, 256>>>(out);
    }
    k_out2<<<128 * 8, 256>>>(out);
}